// round 11
// baseline (speedup 1.0000x reference)
#include <cuda_runtime.h>
#include <cuda_fp16.h>
#include <cstdint>

#define NNODES 50000
#define NEDGES 800000
#define ETOT   (NNODES + NEDGES)
#define HEADS  4
#define HID    64
#define HH     256   // HEADS*HID
#define INC    128
#define OUTC   128
#define NCHUNK ((NNODES + 1023) / 1024)

// ---------------- scratch (device globals; no allocation) ----------------
__device__ __half g_H [NNODES * HH];      // transformed features, fp16 [N,4,64]
__device__ float g_ES  [NNODES * HEADS];
__device__ float g_ED  [NNODES * HEADS];
__device__ float g_F1  [NNODES * HID];
__device__ float g_F2  [NNODES * HID];
__device__ float g_WSD1[INC * 8];
__device__ float g_WSD2[HID * 8];
__device__ __half g_W4 [(size_t)ETOT * HEADS];   // per-edge weights (fp16), CSR order
__device__ int   g_DEG[NNODES];
__device__ int   g_CUR[NNODES];
__device__ int   g_ROW[NNODES + 1];
__device__ int   g_COL[ETOT];             // src per CSR slot
__device__ int   g_CDST[ETOT];            // dst per CSR slot
__device__ int   g_CSUM[NCHUNK + 1];

// ---------------- helpers ----------------
__device__ __forceinline__ uint32_t packh2(float x, float y) {
    __half2 h = __floats2half2_rn(x, y);
    return *reinterpret_cast<uint32_t*>(&h);
}

__device__ __forceinline__ void mma_f16(float* c, const uint32_t* a, const uint32_t* b) {
    asm volatile(
        "mma.sync.aligned.m16n8k16.row.col.f32.f16.f16.f32 "
        "{%0,%1,%2,%3}, {%4,%5,%6,%7}, {%8,%9}, {%0,%1,%2,%3};\n"
        : "+f"(c[0]), "+f"(c[1]), "+f"(c[2]), "+f"(c[3])
        : "r"(a[0]), "r"(a[1]), "r"(a[2]), "r"(a[3]), "r"(b[0]), "r"(b[1]));
}

// ---------------- FP16 tensor-core GEMM: C[M,Nn]=A[M,K]@B[K,Nn] (+bias) -----
// BM=BN=128, BK=16, 256 threads (8 warps, 2Mx4N), warp tile 64x32.
// A smem: [row][k-pair] half2 words, stride ALDW. B smem: TRANSPOSED [n][k-pair]
// half2 words, stride ALDW (k-adjacent halves contiguous for the col fragment).
// Fragment-phase banks g*20+tg mod 32 all distinct -> conflict-free hot LDS.
#define ALDW 20

__global__ __launch_bounds__(256, 2)
void hgemm128(const float* __restrict__ A, const float* __restrict__ B,
              float* __restrict__ C, int M, int Nn, int K,
              const float* __restrict__ bias, int half_out) {
    const int BM = 128, BK = 16;
    __shared__ uint32_t As[2][128 * ALDW];
    __shared__ uint32_t Bs[2][128 * ALDW];

    int tid  = threadIdx.x;
    int brow = blockIdx.y * BM;
    int bcol = blockIdx.x * 128;
    int w    = tid >> 5, lane = tid & 31;
    int wm   = w & 1, wn = w >> 1;
    int g    = lane >> 2, tg = lane & 3;

    int ar = tid >> 2, ac = (tid & 3) * 4;   // A: 4 threads/row, 4 k each; rows ar, ar+64
    int br = tid >> 5, bc = (tid & 31) * 4;  // B: k rows br, br+8; 4 n each

    const int T = K / BK;
    float acc[4][4][4];
    #pragma unroll
    for (int i = 0; i < 4; i++)
        #pragma unroll
        for (int j = 0; j < 4; j++)
            #pragma unroll
            for (int r = 0; r < 4; r++) acc[i][j][r] = 0.f;

    // ---- load tile 0 ----
    {
        float4 va0 = make_float4(0.f,0.f,0.f,0.f), va1 = va0;
        long r0 = brow + ar, r1 = brow + ar + 64;
        if (r0 < M) va0 = *reinterpret_cast<const float4*>(A + r0 * K + ac);
        if (r1 < M) va1 = *reinterpret_cast<const float4*>(A + r1 * K + ac);
        As[0][ar * ALDW + (ac >> 1)]            = packh2(va0.x, va0.y);
        As[0][ar * ALDW + (ac >> 1) + 1]        = packh2(va0.z, va0.w);
        As[0][(ar + 64) * ALDW + (ac >> 1)]     = packh2(va1.x, va1.y);
        As[0][(ar + 64) * ALDW + (ac >> 1) + 1] = packh2(va1.z, va1.w);
        float4 vb0 = *reinterpret_cast<const float4*>(B + (long)br * Nn + bcol + bc);
        float4 vb1 = *reinterpret_cast<const float4*>(B + (long)(br + 8) * Nn + bcol + bc);
        float b0a[4] = {vb0.x, vb0.y, vb0.z, vb0.w};
        float b1a[4] = {vb1.x, vb1.y, vb1.z, vb1.w};
        #pragma unroll
        for (int i = 0; i < 4; i++) {
            reinterpret_cast<__half*>(&Bs[0][(bc + i) * ALDW + (br >> 1)])[br & 1]     = __float2half_rn(b0a[i]);
            reinterpret_cast<__half*>(&Bs[0][(bc + i) * ALDW + (br >> 1) + 4])[br & 1] = __float2half_rn(b1a[i]);
        }
    }
    __syncthreads();

    for (int t = 0; t < T; t++) {
        int buf = t & 1;
        // prefetch next tile into registers
        float4 va0 = make_float4(0.f,0.f,0.f,0.f), va1 = va0, vb0 = va0, vb1 = va0;
        if (t + 1 < T) {
            int k0 = (t + 1) * BK;
            long r0 = brow + ar, r1 = brow + ar + 64;
            if (r0 < M) va0 = *reinterpret_cast<const float4*>(A + r0 * K + k0 + ac);
            if (r1 < M) va1 = *reinterpret_cast<const float4*>(A + r1 * K + k0 + ac);
            vb0 = *reinterpret_cast<const float4*>(B + (long)(k0 + br) * Nn + bcol + bc);
            vb1 = *reinterpret_cast<const float4*>(B + (long)(k0 + br + 8) * Nn + bcol + bc);
        }
        // compute: one m16n8k16 step covers the whole BK=16 tile
        uint32_t af[4][4];
        #pragma unroll
        for (int mt = 0; mt < 4; mt++) {
            int r0 = (wm * 64 + mt * 16 + g) * ALDW + tg;
            af[mt][0] = As[buf][r0];
            af[mt][1] = As[buf][r0 + 8 * ALDW];
            af[mt][2] = As[buf][r0 + 4];
            af[mt][3] = As[buf][r0 + 8 * ALDW + 4];
        }
        uint32_t bf[4][2];
        #pragma unroll
        for (int nt = 0; nt < 4; nt++) {
            int c0 = (wn * 32 + nt * 8 + g) * ALDW + tg;
            bf[nt][0] = Bs[buf][c0];
            bf[nt][1] = Bs[buf][c0 + 4];
        }
        #pragma unroll
        for (int mt = 0; mt < 4; mt++)
            #pragma unroll
            for (int nt = 0; nt < 4; nt++)
                mma_f16(acc[mt][nt], af[mt], bf[nt]);

        if (t + 1 < T) {
            int nb = buf ^ 1;
            As[nb][ar * ALDW + (ac >> 1)]            = packh2(va0.x, va0.y);
            As[nb][ar * ALDW + (ac >> 1) + 1]        = packh2(va0.z, va0.w);
            As[nb][(ar + 64) * ALDW + (ac >> 1)]     = packh2(va1.x, va1.y);
            As[nb][(ar + 64) * ALDW + (ac >> 1) + 1] = packh2(va1.z, va1.w);
            float b0a[4] = {vb0.x, vb0.y, vb0.z, vb0.w};
            float b1a[4] = {vb1.x, vb1.y, vb1.z, vb1.w};
            #pragma unroll
            for (int i = 0; i < 4; i++) {
                reinterpret_cast<__half*>(&Bs[nb][(bc + i) * ALDW + (br >> 1)])[br & 1]     = __float2half_rn(b0a[i]);
                reinterpret_cast<__half*>(&Bs[nb][(bc + i) * ALDW + (br >> 1) + 4])[br & 1] = __float2half_rn(b1a[i]);
            }
            __syncthreads();
        }
    }

    // ---- epilogue (C fragment layout identical to tf32 m16n8k8) ----
    #pragma unroll
    for (int mt = 0; mt < 4; mt++) {
        #pragma unroll
        for (int nt = 0; nt < 4; nt++) {
            int r = brow + wm * 64 + mt * 16 + g;
            int c = bcol + wn * 32 + nt * 8 + tg * 2;
            float bx = 0.f, by = 0.f;
            if (bias) { bx = bias[c]; by = bias[c + 1]; }
            float2 v0 = make_float2(acc[mt][nt][0] + bx, acc[mt][nt][1] + by);
            float2 v1 = make_float2(acc[mt][nt][2] + bx, acc[mt][nt][3] + by);
            if (half_out) {
                __half* Ch = reinterpret_cast<__half*>(C);
                if (r < M)
                    *reinterpret_cast<__half2*>(Ch + (long)r * Nn + c) = __float22half2_rn(v0);
                if (r + 8 < M)
                    *reinterpret_cast<__half2*>(Ch + (long)(r + 8) * Nn + c) = __float22half2_rn(v1);
            } else {
                if (r < M)
                    *reinterpret_cast<float2*>(C + (long)r * Nn + c) = v0;
                if (r + 8 < M)
                    *reinterpret_cast<float2*>(C + (long)(r + 8) * Nn + c) = v1;
            }
        }
    }
}

// ---------------- fold attention vectors into W (both layers, one launch) ---
__global__ void foldw2_k(const float* __restrict__ W1, const float* __restrict__ as1,
                         const float* __restrict__ ad1, float* __restrict__ wsd1,
                         const float* __restrict__ W2, const float* __restrict__ as2,
                         const float* __restrict__ ad2, float* __restrict__ wsd2) {
    int layer = blockIdx.y;
    const float* W   = layer ? W2  : W1;
    const float* as_ = layer ? as2 : as1;
    const float* ad_ = layer ? ad2 : ad1;
    float* wsd = layer ? wsd2 : wsd1;
    int K = layer ? HID : INC;
    int t = blockIdx.x * blockDim.x + threadIdx.x;
    if (t >= K * 8) return;
    int k = t >> 3, j = t & 7, h = j & 3;
    const float* a = ((j < 4) ? as_ : ad_) + h * HID;
    const float* wr = W + (long)k * HH + h * HID;
    float s = 0.f;
    #pragma unroll 16
    for (int c = 0; c < HID; c++) s += wr[c] * a[c];
    wsd[k * 8 + j] = s;
}

// ---------------- skinny scores: es/ed[n][h] = X[n,:] @ Wsd[:,j] ------------
__global__ void sscore_k(const float* __restrict__ X, const float* __restrict__ wsd,
                         float* __restrict__ es, float* __restrict__ ed,
                         int Nn, int K) {
    __shared__ float sW[8][128];
    int tid = threadIdx.x;
    for (int idx = tid; idx < K * 8; idx += blockDim.x) {
        int k = idx >> 3, j = idx & 7;
        sW[j][k] = wsd[k * 8 + j];
    }
    __syncthreads();

    int node = blockIdx.x * 8 + (tid >> 5);
    int lane = tid & 31;
    if (node >= Nn) return;
    int nq = K >> 2;

    float4 xv = make_float4(0.f, 0.f, 0.f, 0.f);
    if (lane < nq)
        xv = reinterpret_cast<const float4*>(X + (long)node * K)[lane];

    float acc[8];
    #pragma unroll
    for (int j = 0; j < 8; j++) {
        float4 wv = make_float4(0.f, 0.f, 0.f, 0.f);
        if (lane < nq)
            wv = *reinterpret_cast<const float4*>(&sW[j][lane * 4]);
        acc[j] = xv.x * wv.x + xv.y * wv.y + xv.z * wv.z + xv.w * wv.w;
    }
    #pragma unroll
    for (int o = 16; o > 0; o >>= 1) {
        #pragma unroll
        for (int j = 0; j < 8; j++)
            acc[j] += __shfl_xor_sync(0xffffffffu, acc[j], o);
    }
    if (lane == 0) {
        *reinterpret_cast<float4*>(es + node * 4) = make_float4(acc[0], acc[1], acc[2], acc[3]);
        *reinterpret_cast<float4*>(ed + node * 4) = make_float4(acc[4], acc[5], acc[6], acc[7]);
    }
}

// ---------------- CSR build ----------------
__global__ void zero2_k(int* __restrict__ a, int* __restrict__ b, int n) {
    int i = blockIdx.x * blockDim.x + threadIdx.x;
    if (i < n) { a[i] = 0; b[i] = 0; }
}

__global__ void deg_k(const int* __restrict__ ei, int* __restrict__ deg,
                      int Ein, int Etot) {
    int e = blockIdx.x * blockDim.x + threadIdx.x;
    if (e >= Etot) return;
    int d = (e < Ein) ? ei[Ein + e] : e - Ein;
    atomicAdd(&deg[d], 1);
}

__global__ void chunksum_k(const int* __restrict__ deg, int* __restrict__ csum, int Nn) {
    __shared__ int wsum[32];
    int t = threadIdx.x, lane = t & 31, wid = t >> 5;
    int i = blockIdx.x * 1024 + t;
    int v = (i < Nn) ? deg[i] : 0;
    #pragma unroll
    for (int o = 16; o > 0; o >>= 1) v += __shfl_xor_sync(0xffffffffu, v, o);
    if (lane == 0) wsum[wid] = v;
    __syncthreads();
    if (wid == 0) {
        int s = wsum[lane];
        #pragma unroll
        for (int o = 16; o > 0; o >>= 1) s += __shfl_xor_sync(0xffffffffu, s, o);
        if (lane == 0) csum[blockIdx.x] = s;
    }
}

// warp-parallel exclusive scan over chunk sums (nchunk ~ 49)
__global__ void scanchunks_k(int* __restrict__ csum, int* __restrict__ rowptr,
                             int nchunk, int Nn) {
    int lane = threadIdx.x;   // 32 threads
    int carry = 0;
    for (int base = 0; base < nchunk; base += 32) {
        int i = base + lane;
        int v = (i < nchunk) ? csum[i] : 0;
        int x = v;
        #pragma unroll
        for (int o = 1; o < 32; o <<= 1) {
            int y = __shfl_up_sync(0xffffffffu, x, o);
            if (lane >= o) x += y;
        }
        if (i < nchunk) csum[i] = carry + x - v;
        carry += __shfl_sync(0xffffffffu, x, 31);
    }
    if (lane == 0) { csum[nchunk] = carry; rowptr[Nn] = carry; }
}

__global__ void rowptr_k(const int* __restrict__ deg, const int* __restrict__ csum,
                         int* __restrict__ rowptr, int Nn) {
    __shared__ int wsum[32];
    int t = threadIdx.x, lane = t & 31, wid = t >> 5;
    int i = blockIdx.x * 1024 + t;
    int v = (i < Nn) ? deg[i] : 0;
    int x = v;
    #pragma unroll
    for (int o = 1; o < 32; o <<= 1) {
        int y = __shfl_up_sync(0xffffffffu, x, o);
        if (lane >= o) x += y;
    }
    if (lane == 31) wsum[wid] = x;
    __syncthreads();
    if (wid == 0) {
        int s = wsum[lane];
        #pragma unroll
        for (int o = 1; o < 32; o <<= 1) {
            int y = __shfl_up_sync(0xffffffffu, s, o);
            if (lane >= o) s += y;
        }
        wsum[lane] = s;
    }
    __syncthreads();
    int off = csum[blockIdx.x] + (wid > 0 ? wsum[wid - 1] : 0);
    if (i < Nn) rowptr[i] = off + x - v;
}

__global__ void fill_k(const int* __restrict__ ei, int* __restrict__ cursor,
                       const int* __restrict__ rowptr, int* __restrict__ colsrc,
                       int* __restrict__ coldst, int Ein, int Etot) {
    int e = blockIdx.x * blockDim.x + threadIdx.x;
    if (e >= Etot) return;
    int s, d;
    if (e < Ein) { s = ei[e]; d = ei[Ein + e]; }
    else         { s = d = e - Ein; }
    int p = atomicAdd(&cursor[d], 1);
    int slot = rowptr[d] + p;
    colsrc[slot] = s;
    coldst[slot] = d;
}

// ---------------- per-edge softmax weights (fp16, CSR order) ----------------
__global__ void edgew_k(const int* __restrict__ colsrc, const int* __restrict__ coldst,
                        const float* __restrict__ es, const float* __restrict__ ed,
                        __half* __restrict__ w4, int Etot) {
    int e = blockIdx.x * blockDim.x + threadIdx.x;
    if (e >= Etot) return;
    int s = colsrc[e], d = coldst[e];
    float4 a = *reinterpret_cast<const float4*>(es + (long)s * 4);
    float4 c = *reinterpret_cast<const float4*>(ed + (long)d * 4);
    float4 r;
    float v;
    v = a.x + c.x; v = (v > 0.f) ? v : 0.2f * v; r.x = __expf(v);
    v = a.y + c.y; v = (v > 0.f) ? v : 0.2f * v; r.y = __expf(v);
    v = a.z + c.z; v = (v > 0.f) ? v : 0.2f * v; r.z = __expf(v);
    v = a.w + c.w; v = (v > 0.f) ? v : 0.2f * v; r.w = __expf(v);
    union { __half2 h[2]; uint2 u; } cv;
    cv.h[0] = __float22half2_rn(make_float2(r.x, r.y));
    cv.h[1] = __float22half2_rn(make_float2(r.z, r.w));
    *reinterpret_cast<uint2*>(w4 + (long)e * 4) = cv.u;
}

// ---------------- fused gather (fp16 H, fp16 weights; lean registers) -------
__global__ void gather_k(const __half* __restrict__ H, const int* __restrict__ rowptr,
                         const int* __restrict__ colsrc, const __half* __restrict__ w4,
                         const float* __restrict__ b, const float* __restrict__ g,
                         const float* __restrict__ be,
                         float* __restrict__ out, int Nn) {
    int warp = (blockIdx.x * blockDim.x + threadIdx.x) >> 5;
    int lane = threadIdx.x & 31;
    if (warp >= Nn) return;
    const int head = lane >> 3;

    float acc[8] = {0.f,0.f,0.f,0.f,0.f,0.f,0.f,0.f};
    float den = 0.f;

    int beg = rowptr[warp], end = rowptr[warp + 1];
    const uint4* __restrict__ H4 = reinterpret_cast<const uint4*>(H);

    int e = beg;
    for (; e + 8 <= end; e += 8) {
        int s[8]; float wv[8];
        #pragma unroll
        for (int u = 0; u < 8; u++) {
            s[u]  = colsrc[e + u];
            wv[u] = __half2float(w4[(long)(e + u) * 4 + head]);
        }
        #pragma unroll
        for (int u = 0; u < 8; u++) {
            uint4 hv = H4[(long)s[u] * 32 + lane];
            const __half2* hp = reinterpret_cast<const __half2*>(&hv);
            float2 f0 = __half22float2(hp[0]);
            float2 f1 = __half22float2(hp[1]);
            float2 f2 = __half22float2(hp[2]);
            float2 f3 = __half22float2(hp[3]);
            den += wv[u];
            acc[0] += wv[u] * f0.x; acc[1] += wv[u] * f0.y;
            acc[2] += wv[u] * f1.x; acc[3] += wv[u] * f1.y;
            acc[4] += wv[u] * f2.x; acc[5] += wv[u] * f2.y;
            acc[6] += wv[u] * f3.x; acc[7] += wv[u] * f3.y;
        }
    }
    for (; e < end; e++) {
        int s0  = colsrc[e];
        float w0 = __half2float(w4[(long)e * 4 + head]);
        uint4 hv = H4[(long)s0 * 32 + lane];
        const __half2* hp = reinterpret_cast<const __half2*>(&hv);
        float2 f0 = __half22float2(hp[0]);
        float2 f1 = __half22float2(hp[1]);
        float2 f2 = __half22float2(hp[2]);
        float2 f3 = __half22float2(hp[3]);
        den += w0;
        acc[0] += w0 * f0.x; acc[1] += w0 * f0.y;
        acc[2] += w0 * f1.x; acc[3] += w0 * f1.y;
        acc[4] += w0 * f2.x; acc[5] += w0 * f2.y;
        acc[6] += w0 * f3.x; acc[7] += w0 * f3.y;
    }

    float r = 1.f / den;     // den = full per-head denominator (broadcast weights)
    float v8[8];
    #pragma unroll
    for (int i = 0; i < 8; i++) v8[i] = acc[i] * r;

    // cross-head sum: lanes L, L^8, L^16, L^24 hold same channels, diff heads
    #pragma unroll
    for (int i = 0; i < 8; i++) {
        v8[i] += __shfl_xor_sync(0xffffffffu, v8[i], 8);
        v8[i] += __shfl_xor_sync(0xffffffffu, v8[i], 16);
    }

    int ch = (lane & 7) * 8;
    #pragma unroll
    for (int i = 0; i < 8; i++) v8[i] = v8[i] * 0.25f + b[ch + i];

    float sum = 0.f, ssq = 0.f;
    #pragma unroll
    for (int i = 0; i < 8; i++) { sum += v8[i]; ssq += v8[i] * v8[i]; }
    #pragma unroll
    for (int o = 16; o > 0; o >>= 1) {
        sum += __shfl_xor_sync(0xffffffffu, sum, o);
        ssq += __shfl_xor_sync(0xffffffffu, ssq, o);
    }
    float mean = sum * (1.f / 256.f);
    float var  = ssq * (1.f / 256.f) - mean * mean;
    float inv  = rsqrtf(var + 1e-5f);

    #pragma unroll
    for (int i = 0; i < 8; i++)
        v8[i] = fmaxf((v8[i] - mean) * inv * g[ch + i] + be[ch + i], 0.f);

    if (lane < 8) {
        float4 o0 = make_float4(v8[0], v8[1], v8[2], v8[3]);
        float4 o1 = make_float4(v8[4], v8[5], v8[6], v8[7]);
        float4* op = reinterpret_cast<float4*>(out + (long)warp * HID + ch);
        op[0] = o0; op[1] = o1;
    }
}

// ---------------------------------------------------------------------------
extern "C" void kernel_launch(void* const* d_in, const int* in_sizes, int n_in,
                              void* d_out, int out_size) {
    const float* x     = (const float*)d_in[0];
    const int*   ei    = (const int*)  d_in[1];
    const float* W1    = (const float*)d_in[2];
    const float* asrc1 = (const float*)d_in[3];
    const float* adst1 = (const float*)d_in[4];
    const float* b1    = (const float*)d_in[5];
    const float* g1    = (const float*)d_in[6];
    const float* be1   = (const float*)d_in[7];
    const float* W2    = (const float*)d_in[8];
    const float* asrc2 = (const float*)d_in[9];
    const float* adst2 = (const float*)d_in[10];
    const float* b2    = (const float*)d_in[11];
    const float* g2    = (const float*)d_in[12];
    const float* be2   = (const float*)d_in[13];
    const float* Wo    = (const float*)d_in[14];
    const float* bo    = (const float*)d_in[15];
    float* out = (float*)d_out;

    const int Nn   = in_sizes[0] / INC;      // 50000
    const int Ein  = in_sizes[1] / 2;        // 800000
    const int Etot = Ein + Nn;               // 850000
    const int nchunk = (Nn + 1023) / 1024;

    __half *H, *W4;
    float *ES, *ED, *F1, *F2, *WSD1, *WSD2;
    int *DEG, *CUR, *ROW, *COL, *CDST, *CSUM;
    cudaGetSymbolAddress((void**)&H,    g_H);
    cudaGetSymbolAddress((void**)&ES,   g_ES);
    cudaGetSymbolAddress((void**)&ED,   g_ED);
    cudaGetSymbolAddress((void**)&F1,   g_F1);
    cudaGetSymbolAddress((void**)&F2,   g_F2);
    cudaGetSymbolAddress((void**)&WSD1, g_WSD1);
    cudaGetSymbolAddress((void**)&WSD2, g_WSD2);
    cudaGetSymbolAddress((void**)&W4,   g_W4);
    cudaGetSymbolAddress((void**)&DEG,  g_DEG);
    cudaGetSymbolAddress((void**)&CUR,  g_CUR);
    cudaGetSymbolAddress((void**)&ROW,  g_ROW);
    cudaGetSymbolAddress((void**)&COL,  g_COL);
    cudaGetSymbolAddress((void**)&CDST, g_CDST);
    cudaGetSymbolAddress((void**)&CSUM, g_CSUM);

    dim3 gemm1_grid(HH / 128, (Nn + 127) / 128);
    dim3 gemm2_grid(HH / 128, (Nn + 127) / 128);
    dim3 gemmo_grid(OUTC / 128, (Nn + 127) / 128);
    int edge_blocks  = (Etot + 255) / 256;
    int node_warpblk = (Nn * 32 + 255) / 256;
    int score_blocks = (Nn + 7) / 8;
    dim3 fold_grid((INC * 8 + 255) / 256, 2);

    // ---------------- CSR build + weight folds ----------------
    zero2_k<<<(Nn + 1023) / 1024, 1024>>>(DEG, CUR, Nn);
    deg_k<<<edge_blocks, 256>>>(ei, DEG, Ein, Etot);
    chunksum_k<<<nchunk, 1024>>>(DEG, CSUM, Nn);
    scanchunks_k<<<1, 32>>>(CSUM, ROW, nchunk, Nn);
    rowptr_k<<<nchunk, 1024>>>(DEG, CSUM, ROW, Nn);
    fill_k<<<edge_blocks, 256>>>(ei, CUR, ROW, COL, CDST, Ein, Etot);
    foldw2_k<<<fold_grid, 256>>>(W1, asrc1, adst1, WSD1, W2, asrc2, adst2, WSD2);

    // ---------------- layer 1 ----------------
    sscore_k<<<score_blocks, 256>>>(x, WSD1, ES, ED, Nn, INC);
    hgemm128<<<gemm1_grid, 256>>>(x, W1, (float*)H, Nn, HH, INC, nullptr, 1);
    edgew_k<<<edge_blocks, 256>>>(COL, CDST, ES, ED, W4, Etot);
    gather_k<<<node_warpblk, 256>>>(H, ROW, COL, W4, b1, g1, be1, F1, Nn);

    // ---------------- layer 2 ----------------
    sscore_k<<<score_blocks, 256>>>(F1, WSD2, ES, ED, Nn, HID);
    hgemm128<<<gemm2_grid, 256>>>(F1, W2, (float*)H, Nn, HH, HID, nullptr, 1);
    edgew_k<<<edge_blocks, 256>>>(COL, CDST, ES, ED, W4, Etot);
    gather_k<<<node_warpblk, 256>>>(H, ROW, COL, W4, b2, g2, be2, F2, Nn);

    // ---------------- output projection (fp32 out) ----------------
    hgemm128<<<gemmo_grid, 256>>>(F2, Wo, out, Nn, OUTC, HID, bo, 0);
}

// round 12
// speedup vs baseline: 1.0817x; 1.0817x over previous
#include <cuda_runtime.h>
#include <cuda_fp16.h>
#include <cstdint>

#define NNODES 50000
#define NEDGES 800000
#define ETOT   (NNODES + NEDGES)
#define HEADS  4
#define HID    64
#define HH     256   // HEADS*HID
#define INC    128
#define OUTC   128
#define NCHUNK ((NNODES + 1023) / 1024)

// ---------------- scratch (device globals; no allocation) ----------------
__device__ __half g_H [NNODES * HH];      // transformed features, fp16 [N,4,64]
__device__ float g_ES  [NNODES * HEADS];
__device__ float g_ED  [NNODES * HEADS];
__device__ float g_F1  [NNODES * HID];
__device__ float g_F2  [NNODES * HID];
__device__ float g_WSD1[INC * 8];
__device__ float g_WSD2[HID * 8];
__device__ __half g_W4 [(size_t)ETOT * HEADS];   // per-edge weights (fp16), CSR order
__device__ int   g_DEG[NNODES];
__device__ int   g_CUR[NNODES];
__device__ int   g_ROW[NNODES + 1];
__device__ int   g_COL[ETOT];             // src per CSR slot
__device__ int   g_CDST[ETOT];            // dst per CSR slot
__device__ int   g_CSUM[NCHUNK + 1];

// ---------------- helpers ----------------
__device__ __forceinline__ uint32_t f2tf32(float f) {
    uint32_t u;
    asm("cvt.rna.tf32.f32 %0, %1;" : "=r"(u) : "f"(f));
    return u;
}

__device__ __forceinline__ void mma_tf32(float* c, const uint32_t* a, const uint32_t* b) {
    asm volatile(
        "mma.sync.aligned.m16n8k8.row.col.f32.tf32.tf32.f32 "
        "{%0,%1,%2,%3}, {%4,%5,%6,%7}, {%8,%9}, {%0,%1,%2,%3};\n"
        : "+f"(c[0]), "+f"(c[1]), "+f"(c[2]), "+f"(c[3])
        : "r"(a[0]), "r"(a[1]), "r"(a[2]), "r"(a[3]), "r"(b[0]), "r"(b[1]));
}

// ---------------- TF32 tensor-core GEMM, optional fp16 output (R10) ---------
#define ALD 20
#define BLD 136

__global__ __launch_bounds__(256, 2)
void tgemm128(const float* __restrict__ A, const float* __restrict__ B,
              float* __restrict__ C, int M, int Nn, int K,
              const float* __restrict__ bias, int half_out) {
    const int BM = 128, BK = 16;
    __shared__ uint32_t As[2][BM * ALD];
    __shared__ uint32_t Bs[2][BK * BLD];

    int tid  = threadIdx.x;
    int brow = blockIdx.y * BM;
    int bcol = blockIdx.x * 128;
    int w    = tid >> 5, lane = tid & 31;
    int wm   = w & 1, wn = w >> 1;
    int g    = lane >> 2, tg = lane & 3;

    int ar = tid >> 2, ac = (tid & 3) * 4;
    int br = tid >> 5, bc = (tid & 31) * 4;

    const int T = K / BK;
    float acc[4][4][4];
    #pragma unroll
    for (int i = 0; i < 4; i++)
        #pragma unroll
        for (int j = 0; j < 4; j++)
            #pragma unroll
            for (int r = 0; r < 4; r++) acc[i][j][r] = 0.f;

    {
        float4 va0 = make_float4(0.f,0.f,0.f,0.f), va1 = va0;
        long r0 = brow + ar, r1 = brow + ar + 64;
        if (r0 < M) va0 = *reinterpret_cast<const float4*>(A + r0 * K + ac);
        if (r1 < M) va1 = *reinterpret_cast<const float4*>(A + r1 * K + ac);
        uint32_t* d0 = &As[0][ar * ALD + ac];
        d0[0]=f2tf32(va0.x); d0[1]=f2tf32(va0.y); d0[2]=f2tf32(va0.z); d0[3]=f2tf32(va0.w);
        uint32_t* d1 = &As[0][(ar + 64) * ALD + ac];
        d1[0]=f2tf32(va1.x); d1[1]=f2tf32(va1.y); d1[2]=f2tf32(va1.z); d1[3]=f2tf32(va1.w);
        float4 vb0 = *reinterpret_cast<const float4*>(B + (long)br * Nn + bcol + bc);
        float4 vb1 = *reinterpret_cast<const float4*>(B + (long)(br + 8) * Nn + bcol + bc);
        uint32_t* e0 = &Bs[0][br * BLD + bc];
        e0[0]=f2tf32(vb0.x); e0[1]=f2tf32(vb0.y); e0[2]=f2tf32(vb0.z); e0[3]=f2tf32(vb0.w);
        uint32_t* e1 = &Bs[0][(br + 8) * BLD + bc];
        e1[0]=f2tf32(vb1.x); e1[1]=f2tf32(vb1.y); e1[2]=f2tf32(vb1.z); e1[3]=f2tf32(vb1.w);
    }
    __syncthreads();

    for (int t = 0; t < T; t++) {
        int buf = t & 1;
        float4 va0 = make_float4(0.f,0.f,0.f,0.f), va1 = va0, vb0 = va0, vb1 = va0;
        if (t + 1 < T) {
            int k0 = (t + 1) * BK;
            long r0 = brow + ar, r1 = brow + ar + 64;
            if (r0 < M) va0 = *reinterpret_cast<const float4*>(A + r0 * K + k0 + ac);
            if (r1 < M) va1 = *reinterpret_cast<const float4*>(A + r1 * K + k0 + ac);
            vb0 = *reinterpret_cast<const float4*>(B + (long)(k0 + br) * Nn + bcol + bc);
            vb1 = *reinterpret_cast<const float4*>(B + (long)(k0 + br + 8) * Nn + bcol + bc);
        }
        #pragma unroll
        for (int kk = 0; kk < BK; kk += 8) {
            uint32_t af[4][4];
            #pragma unroll
            for (int mt = 0; mt < 4; mt++) {
                int r0 = (wm * 64 + mt * 16 + g) * ALD + kk + tg;
                af[mt][0] = As[buf][r0];
                af[mt][1] = As[buf][r0 + 8 * ALD];
                af[mt][2] = As[buf][r0 + 4];
                af[mt][3] = As[buf][r0 + 8 * ALD + 4];
            }
            uint32_t bf[4][2];
            #pragma unroll
            for (int nt = 0; nt < 4; nt++) {
                int c0 = wn * 32 + nt * 8 + g;
                bf[nt][0] = Bs[buf][(kk + tg) * BLD + c0];
                bf[nt][1] = Bs[buf][(kk + tg + 4) * BLD + c0];
            }
            #pragma unroll
            for (int mt = 0; mt < 4; mt++)
                #pragma unroll
                for (int nt = 0; nt < 4; nt++)
                    mma_tf32(acc[mt][nt], af[mt], bf[nt]);
        }
        if (t + 1 < T) {
            int nb = buf ^ 1;
            uint32_t* d0 = &As[nb][ar * ALD + ac];
            d0[0]=f2tf32(va0.x); d0[1]=f2tf32(va0.y); d0[2]=f2tf32(va0.z); d0[3]=f2tf32(va0.w);
            uint32_t* d1 = &As[nb][(ar + 64) * ALD + ac];
            d1[0]=f2tf32(va1.x); d1[1]=f2tf32(va1.y); d1[2]=f2tf32(va1.z); d1[3]=f2tf32(va1.w);
            uint32_t* e0 = &Bs[nb][br * BLD + bc];
            e0[0]=f2tf32(vb0.x); e0[1]=f2tf32(vb0.y); e0[2]=f2tf32(vb0.z); e0[3]=f2tf32(vb0.w);
            uint32_t* e1 = &Bs[nb][(br + 8) * BLD + bc];
            e1[0]=f2tf32(vb1.x); e1[1]=f2tf32(vb1.y); e1[2]=f2tf32(vb1.z); e1[3]=f2tf32(vb1.w);
            __syncthreads();
        }
    }

    #pragma unroll
    for (int mt = 0; mt < 4; mt++) {
        #pragma unroll
        for (int nt = 0; nt < 4; nt++) {
            int r = brow + wm * 64 + mt * 16 + g;
            int c = bcol + wn * 32 + nt * 8 + tg * 2;
            float bx = 0.f, by = 0.f;
            if (bias) { bx = bias[c]; by = bias[c + 1]; }
            float2 v0 = make_float2(acc[mt][nt][0] + bx, acc[mt][nt][1] + by);
            float2 v1 = make_float2(acc[mt][nt][2] + bx, acc[mt][nt][3] + by);
            if (half_out) {
                __half* Ch = reinterpret_cast<__half*>(C);
                if (r < M)
                    *reinterpret_cast<__half2*>(Ch + (long)r * Nn + c) = __float22half2_rn(v0);
                if (r + 8 < M)
                    *reinterpret_cast<__half2*>(Ch + (long)(r + 8) * Nn + c) = __float22half2_rn(v1);
            } else {
                if (r < M)
                    *reinterpret_cast<float2*>(C + (long)r * Nn + c) = v0;
                if (r + 8 < M)
                    *reinterpret_cast<float2*>(C + (long)(r + 8) * Nn + c) = v1;
            }
        }
    }
}

// ---------------- fold attention vectors into W (both layers, one launch) ---
__global__ void foldw2_k(const float* __restrict__ W1, const float* __restrict__ as1,
                         const float* __restrict__ ad1, float* __restrict__ wsd1,
                         const float* __restrict__ W2, const float* __restrict__ as2,
                         const float* __restrict__ ad2, float* __restrict__ wsd2) {
    int layer = blockIdx.y;
    const float* W   = layer ? W2  : W1;
    const float* as_ = layer ? as2 : as1;
    const float* ad_ = layer ? ad2 : ad1;
    float* wsd = layer ? wsd2 : wsd1;
    int K = layer ? HID : INC;
    int t = blockIdx.x * blockDim.x + threadIdx.x;
    if (t >= K * 8) return;
    int k = t >> 3, j = t & 7, h = j & 3;
    const float* a = ((j < 4) ? as_ : ad_) + h * HID;
    const float* wr = W + (long)k * HH + h * HID;
    float s = 0.f;
    #pragma unroll 16
    for (int c = 0; c < HID; c++) s += wr[c] * a[c];
    wsd[k * 8 + j] = s;
}

// ---------------- skinny scores: es/ed[n][h] = X[n,:] @ Wsd[:,j] ------------
__global__ void sscore_k(const float* __restrict__ X, const float* __restrict__ wsd,
                         float* __restrict__ es, float* __restrict__ ed,
                         int Nn, int K) {
    __shared__ float sW[8][128];
    int tid = threadIdx.x;
    for (int idx = tid; idx < K * 8; idx += blockDim.x) {
        int k = idx >> 3, j = idx & 7;
        sW[j][k] = wsd[k * 8 + j];
    }
    __syncthreads();

    int node = blockIdx.x * 8 + (tid >> 5);
    int lane = tid & 31;
    if (node >= Nn) return;
    int nq = K >> 2;

    float4 xv = make_float4(0.f, 0.f, 0.f, 0.f);
    if (lane < nq)
        xv = reinterpret_cast<const float4*>(X + (long)node * K)[lane];

    float acc[8];
    #pragma unroll
    for (int j = 0; j < 8; j++) {
        float4 wv = make_float4(0.f, 0.f, 0.f, 0.f);
        if (lane < nq)
            wv = *reinterpret_cast<const float4*>(&sW[j][lane * 4]);
        acc[j] = xv.x * wv.x + xv.y * wv.y + xv.z * wv.z + xv.w * wv.w;
    }
    #pragma unroll
    for (int o = 16; o > 0; o >>= 1) {
        #pragma unroll
        for (int j = 0; j < 8; j++)
            acc[j] += __shfl_xor_sync(0xffffffffu, acc[j], o);
    }
    if (lane == 0) {
        *reinterpret_cast<float4*>(es + node * 4) = make_float4(acc[0], acc[1], acc[2], acc[3]);
        *reinterpret_cast<float4*>(ed + node * 4) = make_float4(acc[4], acc[5], acc[6], acc[7]);
    }
}

// ---------------- CSR build ----------------
__global__ void zero2_k(int* __restrict__ a, int* __restrict__ b, int n) {
    int i = blockIdx.x * blockDim.x + threadIdx.x;
    if (i < n) { a[i] = 0; b[i] = 0; }
}

__global__ void deg_k(const int* __restrict__ ei, int* __restrict__ deg,
                      int Ein, int Etot) {
    int e = blockIdx.x * blockDim.x + threadIdx.x;
    if (e >= Etot) return;
    int d = (e < Ein) ? ei[Ein + e] : e - Ein;
    atomicAdd(&deg[d], 1);
}

__global__ void chunksum_k(const int* __restrict__ deg, int* __restrict__ csum, int Nn) {
    __shared__ int wsum[32];
    int t = threadIdx.x, lane = t & 31, wid = t >> 5;
    int i = blockIdx.x * 1024 + t;
    int v = (i < Nn) ? deg[i] : 0;
    #pragma unroll
    for (int o = 16; o > 0; o >>= 1) v += __shfl_xor_sync(0xffffffffu, v, o);
    if (lane == 0) wsum[wid] = v;
    __syncthreads();
    if (wid == 0) {
        int s = wsum[lane];
        #pragma unroll
        for (int o = 16; o > 0; o >>= 1) s += __shfl_xor_sync(0xffffffffu, s, o);
        if (lane == 0) csum[blockIdx.x] = s;
    }
}

// rowptr with inlined chunk-offset reduction (csum holds RAW chunk sums).
// Each block reduces csum[0..blockIdx) itself; last block writes rowptr[Nn].
__global__ void rowptr_k(const int* __restrict__ deg, const int* __restrict__ csum,
                         int* __restrict__ rowptr, int Nn, int nchunk) {
    __shared__ int wsum[32];
    __shared__ int chunk_off;
    int t = threadIdx.x, lane = t & 31, wid = t >> 5;

    if (wid == 0) {
        int v = 0;
        for (int i = lane; i < blockIdx.x; i += 32) v += csum[i];
        #pragma unroll
        for (int o = 16; o > 0; o >>= 1) v += __shfl_xor_sync(0xffffffffu, v, o);
        if (lane == 0) chunk_off = v;
        if (blockIdx.x == nchunk - 1) {
            int tot = 0;
            for (int i = lane; i < nchunk; i += 32) tot += csum[i];
            #pragma unroll
            for (int o = 16; o > 0; o >>= 1) tot += __shfl_xor_sync(0xffffffffu, tot, o);
            if (lane == 0) rowptr[Nn] = tot;
        }
    }

    int i = blockIdx.x * 1024 + t;
    int v = (i < Nn) ? deg[i] : 0;
    int x = v;
    #pragma unroll
    for (int o = 1; o < 32; o <<= 1) {
        int y = __shfl_up_sync(0xffffffffu, x, o);
        if (lane >= o) x += y;
    }
    if (lane == 31) wsum[wid] = x;
    __syncthreads();
    if (wid == 0) {
        int s = wsum[lane];
        #pragma unroll
        for (int o = 1; o < 32; o <<= 1) {
            int y = __shfl_up_sync(0xffffffffu, s, o);
            if (lane >= o) s += y;
        }
        wsum[lane] = s;
    }
    __syncthreads();
    int off = chunk_off + (wid > 0 ? wsum[wid - 1] : 0);
    if (i < Nn) rowptr[i] = off + x - v;
}

// ---------------- CSR fill + fused layer-1 edge weights ----------------
// sscore1 runs BEFORE this, so es/ed (layer 1) are ready; computes w4 inline.
__global__ void fillw_k(const int* __restrict__ ei, int* __restrict__ cursor,
                        const int* __restrict__ rowptr, int* __restrict__ colsrc,
                        int* __restrict__ coldst,
                        const float* __restrict__ es, const float* __restrict__ ed,
                        __half* __restrict__ w4, int Ein, int Etot) {
    int e = blockIdx.x * blockDim.x + threadIdx.x;
    if (e >= Etot) return;
    int s, d;
    if (e < Ein) { s = ei[e]; d = ei[Ein + e]; }
    else         { s = d = e - Ein; }
    int p = atomicAdd(&cursor[d], 1);
    int slot = rowptr[d] + p;
    colsrc[slot] = s;
    coldst[slot] = d;

    float4 a = *reinterpret_cast<const float4*>(es + (long)s * 4);
    float4 c = *reinterpret_cast<const float4*>(ed + (long)d * 4);
    float4 r;
    float v;
    v = a.x + c.x; v = (v > 0.f) ? v : 0.2f * v; r.x = __expf(v);
    v = a.y + c.y; v = (v > 0.f) ? v : 0.2f * v; r.y = __expf(v);
    v = a.z + c.z; v = (v > 0.f) ? v : 0.2f * v; r.z = __expf(v);
    v = a.w + c.w; v = (v > 0.f) ? v : 0.2f * v; r.w = __expf(v);
    union { __half2 h[2]; uint2 u; } cv;
    cv.h[0] = __float22half2_rn(make_float2(r.x, r.y));
    cv.h[1] = __float22half2_rn(make_float2(r.z, r.w));
    *reinterpret_cast<uint2*>(w4 + (long)slot * 4) = cv.u;
}

// ---------------- per-edge softmax weights (fp16, CSR order; layer 2) -------
__global__ void edgew_k(const int* __restrict__ colsrc, const int* __restrict__ coldst,
                        const float* __restrict__ es, const float* __restrict__ ed,
                        __half* __restrict__ w4, int Etot) {
    int e = blockIdx.x * blockDim.x + threadIdx.x;
    if (e >= Etot) return;
    int s = colsrc[e], d = coldst[e];
    float4 a = *reinterpret_cast<const float4*>(es + (long)s * 4);
    float4 c = *reinterpret_cast<const float4*>(ed + (long)d * 4);
    float4 r;
    float v;
    v = a.x + c.x; v = (v > 0.f) ? v : 0.2f * v; r.x = __expf(v);
    v = a.y + c.y; v = (v > 0.f) ? v : 0.2f * v; r.y = __expf(v);
    v = a.z + c.z; v = (v > 0.f) ? v : 0.2f * v; r.z = __expf(v);
    v = a.w + c.w; v = (v > 0.f) ? v : 0.2f * v; r.w = __expf(v);
    union { __half2 h[2]; uint2 u; } cv;
    cv.h[0] = __float22half2_rn(make_float2(r.x, r.y));
    cv.h[1] = __float22half2_rn(make_float2(r.z, r.w));
    *reinterpret_cast<uint2*>(w4 + (long)e * 4) = cv.u;
}

// ---------------- fused gather (fp16 H, fp16 weights; lean registers) -------
__global__ void gather_k(const __half* __restrict__ H, const int* __restrict__ rowptr,
                         const int* __restrict__ colsrc, const __half* __restrict__ w4,
                         const float* __restrict__ b, const float* __restrict__ g,
                         const float* __restrict__ be,
                         float* __restrict__ out, int Nn) {
    int warp = (blockIdx.x * blockDim.x + threadIdx.x) >> 5;
    int lane = threadIdx.x & 31;
    if (warp >= Nn) return;
    const int head = lane >> 3;

    float acc[8] = {0.f,0.f,0.f,0.f,0.f,0.f,0.f,0.f};
    float den = 0.f;

    int beg = rowptr[warp], end = rowptr[warp + 1];
    const uint4* __restrict__ H4 = reinterpret_cast<const uint4*>(H);

    int e = beg;
    for (; e + 8 <= end; e += 8) {
        int s[8]; float wv[8];
        #pragma unroll
        for (int u = 0; u < 8; u++) {
            s[u]  = colsrc[e + u];
            wv[u] = __half2float(w4[(long)(e + u) * 4 + head]);
        }
        #pragma unroll
        for (int u = 0; u < 8; u++) {
            uint4 hv = H4[(long)s[u] * 32 + lane];
            const __half2* hp = reinterpret_cast<const __half2*>(&hv);
            float2 f0 = __half22float2(hp[0]);
            float2 f1 = __half22float2(hp[1]);
            float2 f2 = __half22float2(hp[2]);
            float2 f3 = __half22float2(hp[3]);
            den += wv[u];
            acc[0] += wv[u] * f0.x; acc[1] += wv[u] * f0.y;
            acc[2] += wv[u] * f1.x; acc[3] += wv[u] * f1.y;
            acc[4] += wv[u] * f2.x; acc[5] += wv[u] * f2.y;
            acc[6] += wv[u] * f3.x; acc[7] += wv[u] * f3.y;
        }
    }
    for (; e < end; e++) {
        int s0  = colsrc[e];
        float w0 = __half2float(w4[(long)e * 4 + head]);
        uint4 hv = H4[(long)s0 * 32 + lane];
        const __half2* hp = reinterpret_cast<const __half2*>(&hv);
        float2 f0 = __half22float2(hp[0]);
        float2 f1 = __half22float2(hp[1]);
        float2 f2 = __half22float2(hp[2]);
        float2 f3 = __half22float2(hp[3]);
        den += w0;
        acc[0] += w0 * f0.x; acc[1] += w0 * f0.y;
        acc[2] += w0 * f1.x; acc[3] += w0 * f1.y;
        acc[4] += w0 * f2.x; acc[5] += w0 * f2.y;
        acc[6] += w0 * f3.x; acc[7] += w0 * f3.y;
    }

    float r = 1.f / den;     // den = full per-head denominator (broadcast weights)
    float v8[8];
    #pragma unroll
    for (int i = 0; i < 8; i++) v8[i] = acc[i] * r;

    // cross-head sum: lanes L, L^8, L^16, L^24 hold same channels, diff heads
    #pragma unroll
    for (int i = 0; i < 8; i++) {
        v8[i] += __shfl_xor_sync(0xffffffffu, v8[i], 8);
        v8[i] += __shfl_xor_sync(0xffffffffu, v8[i], 16);
    }

    int ch = (lane & 7) * 8;
    #pragma unroll
    for (int i = 0; i < 8; i++) v8[i] = v8[i] * 0.25f + b[ch + i];

    float sum = 0.f, ssq = 0.f;
    #pragma unroll
    for (int i = 0; i < 8; i++) { sum += v8[i]; ssq += v8[i] * v8[i]; }
    #pragma unroll
    for (int o = 16; o > 0; o >>= 1) {
        sum += __shfl_xor_sync(0xffffffffu, sum, o);
        ssq += __shfl_xor_sync(0xffffffffu, ssq, o);
    }
    float mean = sum * (1.f / 256.f);
    float var  = ssq * (1.f / 256.f) - mean * mean;
    float inv  = rsqrtf(var + 1e-5f);

    #pragma unroll
    for (int i = 0; i < 8; i++)
        v8[i] = fmaxf((v8[i] - mean) * inv * g[ch + i] + be[ch + i], 0.f);

    if (lane < 8) {
        float4 o0 = make_float4(v8[0], v8[1], v8[2], v8[3]);
        float4 o1 = make_float4(v8[4], v8[5], v8[6], v8[7]);
        float4* op = reinterpret_cast<float4*>(out + (long)warp * HID + ch);
        op[0] = o0; op[1] = o1;
    }
}

// ---------------------------------------------------------------------------
extern "C" void kernel_launch(void* const* d_in, const int* in_sizes, int n_in,
                              void* d_out, int out_size) {
    const float* x     = (const float*)d_in[0];
    const int*   ei    = (const int*)  d_in[1];
    const float* W1    = (const float*)d_in[2];
    const float* asrc1 = (const float*)d_in[3];
    const float* adst1 = (const float*)d_in[4];
    const float* b1    = (const float*)d_in[5];
    const float* g1    = (const float*)d_in[6];
    const float* be1   = (const float*)d_in[7];
    const float* W2    = (const float*)d_in[8];
    const float* asrc2 = (const float*)d_in[9];
    const float* adst2 = (const float*)d_in[10];
    const float* b2    = (const float*)d_in[11];
    const float* g2    = (const float*)d_in[12];
    const float* be2   = (const float*)d_in[13];
    const float* Wo    = (const float*)d_in[14];
    const float* bo    = (const float*)d_in[15];
    float* out = (float*)d_out;

    const int Nn   = in_sizes[0] / INC;      // 50000
    const int Ein  = in_sizes[1] / 2;        // 800000
    const int Etot = Ein + Nn;               // 850000
    const int nchunk = (Nn + 1023) / 1024;

    __half *H, *W4;
    float *ES, *ED, *F1, *F2, *WSD1, *WSD2;
    int *DEG, *CUR, *ROW, *COL, *CDST, *CSUM;
    cudaGetSymbolAddress((void**)&H,    g_H);
    cudaGetSymbolAddress((void**)&ES,   g_ES);
    cudaGetSymbolAddress((void**)&ED,   g_ED);
    cudaGetSymbolAddress((void**)&F1,   g_F1);
    cudaGetSymbolAddress((void**)&F2,   g_F2);
    cudaGetSymbolAddress((void**)&WSD1, g_WSD1);
    cudaGetSymbolAddress((void**)&WSD2, g_WSD2);
    cudaGetSymbolAddress((void**)&W4,   g_W4);
    cudaGetSymbolAddress((void**)&DEG,  g_DEG);
    cudaGetSymbolAddress((void**)&CUR,  g_CUR);
    cudaGetSymbolAddress((void**)&ROW,  g_ROW);
    cudaGetSymbolAddress((void**)&COL,  g_COL);
    cudaGetSymbolAddress((void**)&CDST, g_CDST);
    cudaGetSymbolAddress((void**)&CSUM, g_CSUM);

    dim3 gemm1_grid(HH / 128, (Nn + 127) / 128);
    dim3 gemm2_grid(HH / 128, (Nn + 127) / 128);
    dim3 gemmo_grid(OUTC / 128, (Nn + 127) / 128);
    int edge_blocks  = (Etot + 255) / 256;
    int node_warpblk = (Nn * 32 + 255) / 256;
    int score_blocks = (Nn + 7) / 8;
    dim3 fold_grid((INC * 8 + 255) / 256, 2);

    // ---------------- CSR build + weight folds + layer-1 scores -------------
    zero2_k<<<(Nn + 1023) / 1024, 1024>>>(DEG, CUR, Nn);
    deg_k<<<edge_blocks, 256>>>(ei, DEG, Ein, Etot);
    chunksum_k<<<nchunk, 1024>>>(DEG, CSUM, Nn);
    rowptr_k<<<nchunk, 1024>>>(DEG, CSUM, ROW, Nn, nchunk);
    foldw2_k<<<fold_grid, 256>>>(W1, asrc1, adst1, WSD1, W2, asrc2, adst2, WSD2);
    sscore_k<<<score_blocks, 256>>>(x, WSD1, ES, ED, Nn, INC);
    // fill CSR + layer-1 edge weights in one pass
    fillw_k<<<edge_blocks, 256>>>(ei, CUR, ROW, COL, CDST, ES, ED, W4, Ein, Etot);

    // ---------------- layer 1 ----------------
    tgemm128<<<gemm1_grid, 256>>>(x, W1, (float*)H, Nn, HH, INC, nullptr, 1);
    gather_k<<<node_warpblk, 256>>>(H, ROW, COL, W4, b1, g1, be1, F1, Nn);

    // ---------------- layer 2 ----------------
    sscore_k<<<score_blocks, 256>>>(F1, WSD2, ES, ED, Nn, HID);
    tgemm128<<<gemm2_grid, 256>>>(F1, W2, (float*)H, Nn, HH, HID, nullptr, 1);
    edgew_k<<<edge_blocks, 256>>>(COL, CDST, ES, ED, W4, Etot);
    gather_k<<<node_warpblk, 256>>>(H, ROW, COL, W4, b2, g2, be2, F2, Nn);

    // ---------------- output projection (fp32 out) ----------------
    tgemm128<<<gemmo_grid, 256>>>(F2, Wo, out, Nn, OUTC, HID, bo, 0);
}

// round 14
// speedup vs baseline: 1.1055x; 1.0220x over previous
#include <cuda_runtime.h>
#include <cuda_fp16.h>
#include <cstdint>

#define NNODES 50000
#define NEDGES 800000
#define ETOT   (NNODES + NEDGES)
#define HEADS  4
#define HID    64
#define HH     256   // HEADS*HID
#define INC    128
#define OUTC   128
#define NCHUNK ((NNODES + 1023) / 1024)

// ---------------- scratch (device globals; no allocation) ----------------
__device__ __half g_H [NNODES * HH];      // transformed features, fp16 [N,4,64]
__device__ float g_ES  [NNODES * HEADS];
__device__ float g_ED  [NNODES * HEADS];
__device__ float g_F1  [NNODES * HID];
__device__ float g_F2  [NNODES * HID];
__device__ float g_WSD1[INC * 8];
__device__ float g_WSD2[HID * 8];
__device__ __half g_W4 [(size_t)ETOT * HEADS];   // per-edge weights (fp16), CSR order
__device__ int   g_DEG[NNODES];
__device__ int   g_CUR[NNODES];
__device__ int   g_ROW[NNODES + 1];
__device__ int   g_COL[ETOT];             // src per CSR slot
__device__ int   g_CDST[ETOT];            // dst per CSR slot
__device__ int   g_CSUM[NCHUNK + 1];

// ---------------- helpers ----------------
__device__ __forceinline__ uint32_t f2tf32(float f) {
    uint32_t u;
    asm("cvt.rna.tf32.f32 %0, %1;" : "=r"(u) : "f"(f));
    return u;
}

__device__ __forceinline__ void mma_tf32(float* c, const uint32_t* a, const uint32_t* b) {
    asm volatile(
        "mma.sync.aligned.m16n8k8.row.col.f32.tf32.tf32.f32 "
        "{%0,%1,%2,%3}, {%4,%5,%6,%7}, {%8,%9}, {%0,%1,%2,%3};\n"
        : "+f"(c[0]), "+f"(c[1]), "+f"(c[2]), "+f"(c[3])
        : "r"(a[0]), "r"(a[1]), "r"(a[2]), "r"(a[3]), "r"(b[0]), "r"(b[1]));
}

// ---------------- TF32 tensor-core GEMM, optional fp16 output (R10) ---------
#define ALD 20
#define BLD 136

__global__ __launch_bounds__(256, 2)
void tgemm128(const float* __restrict__ A, const float* __restrict__ B,
              float* __restrict__ C, int M, int Nn, int K,
              const float* __restrict__ bias, int half_out) {
    const int BM = 128, BK = 16;
    __shared__ uint32_t As[2][BM * ALD];
    __shared__ uint32_t Bs[2][BK * BLD];

    int tid  = threadIdx.x;
    int brow = blockIdx.y * BM;
    int bcol = blockIdx.x * 128;
    int w    = tid >> 5, lane = tid & 31;
    int wm   = w & 1, wn = w >> 1;
    int g    = lane >> 2, tg = lane & 3;

    int ar = tid >> 2, ac = (tid & 3) * 4;
    int br = tid >> 5, bc = (tid & 31) * 4;

    const int T = K / BK;
    float acc[4][4][4];
    #pragma unroll
    for (int i = 0; i < 4; i++)
        #pragma unroll
        for (int j = 0; j < 4; j++)
            #pragma unroll
            for (int r = 0; r < 4; r++) acc[i][j][r] = 0.f;

    {
        float4 va0 = make_float4(0.f,0.f,0.f,0.f), va1 = va0;
        long r0 = brow + ar, r1 = brow + ar + 64;
        if (r0 < M) va0 = *reinterpret_cast<const float4*>(A + r0 * K + ac);
        if (r1 < M) va1 = *reinterpret_cast<const float4*>(A + r1 * K + ac);
        uint32_t* d0 = &As[0][ar * ALD + ac];
        d0[0]=f2tf32(va0.x); d0[1]=f2tf32(va0.y); d0[2]=f2tf32(va0.z); d0[3]=f2tf32(va0.w);
        uint32_t* d1 = &As[0][(ar + 64) * ALD + ac];
        d1[0]=f2tf32(va1.x); d1[1]=f2tf32(va1.y); d1[2]=f2tf32(va1.z); d1[3]=f2tf32(va1.w);
        float4 vb0 = *reinterpret_cast<const float4*>(B + (long)br * Nn + bcol + bc);
        float4 vb1 = *reinterpret_cast<const float4*>(B + (long)(br + 8) * Nn + bcol + bc);
        uint32_t* e0 = &Bs[0][br * BLD + bc];
        e0[0]=f2tf32(vb0.x); e0[1]=f2tf32(vb0.y); e0[2]=f2tf32(vb0.z); e0[3]=f2tf32(vb0.w);
        uint32_t* e1 = &Bs[0][(br + 8) * BLD + bc];
        e1[0]=f2tf32(vb1.x); e1[1]=f2tf32(vb1.y); e1[2]=f2tf32(vb1.z); e1[3]=f2tf32(vb1.w);
    }
    __syncthreads();

    for (int t = 0; t < T; t++) {
        int buf = t & 1;
        float4 va0 = make_float4(0.f,0.f,0.f,0.f), va1 = va0, vb0 = va0, vb1 = va0;
        if (t + 1 < T) {
            int k0 = (t + 1) * BK;
            long r0 = brow + ar, r1 = brow + ar + 64;
            if (r0 < M) va0 = *reinterpret_cast<const float4*>(A + r0 * K + k0 + ac);
            if (r1 < M) va1 = *reinterpret_cast<const float4*>(A + r1 * K + k0 + ac);
            vb0 = *reinterpret_cast<const float4*>(B + (long)(k0 + br) * Nn + bcol + bc);
            vb1 = *reinterpret_cast<const float4*>(B + (long)(k0 + br + 8) * Nn + bcol + bc);
        }
        #pragma unroll
        for (int kk = 0; kk < BK; kk += 8) {
            uint32_t af[4][4];
            #pragma unroll
            for (int mt = 0; mt < 4; mt++) {
                int r0 = (wm * 64 + mt * 16 + g) * ALD + kk + tg;
                af[mt][0] = As[buf][r0];
                af[mt][1] = As[buf][r0 + 8 * ALD];
                af[mt][2] = As[buf][r0 + 4];
                af[mt][3] = As[buf][r0 + 8 * ALD + 4];
            }
            uint32_t bf[4][2];
            #pragma unroll
            for (int nt = 0; nt < 4; nt++) {
                int c0 = wn * 32 + nt * 8 + g;
                bf[nt][0] = Bs[buf][(kk + tg) * BLD + c0];
                bf[nt][1] = Bs[buf][(kk + tg + 4) * BLD + c0];
            }
            #pragma unroll
            for (int mt = 0; mt < 4; mt++)
                #pragma unroll
                for (int nt = 0; nt < 4; nt++)
                    mma_tf32(acc[mt][nt], af[mt], bf[nt]);
        }
        if (t + 1 < T) {
            int nb = buf ^ 1;
            uint32_t* d0 = &As[nb][ar * ALD + ac];
            d0[0]=f2tf32(va0.x); d0[1]=f2tf32(va0.y); d0[2]=f2tf32(va0.z); d0[3]=f2tf32(va0.w);
            uint32_t* d1 = &As[nb][(ar + 64) * ALD + ac];
            d1[0]=f2tf32(va1.x); d1[1]=f2tf32(va1.y); d1[2]=f2tf32(va1.z); d1[3]=f2tf32(va1.w);
            uint32_t* e0 = &Bs[nb][br * BLD + bc];
            e0[0]=f2tf32(vb0.x); e0[1]=f2tf32(vb0.y); e0[2]=f2tf32(vb0.z); e0[3]=f2tf32(vb0.w);
            uint32_t* e1 = &Bs[nb][(br + 8) * BLD + bc];
            e1[0]=f2tf32(vb1.x); e1[1]=f2tf32(vb1.y); e1[2]=f2tf32(vb1.z); e1[3]=f2tf32(vb1.w);
            __syncthreads();
        }
    }

    #pragma unroll
    for (int mt = 0; mt < 4; mt++) {
        #pragma unroll
        for (int nt = 0; nt < 4; nt++) {
            int r = brow + wm * 64 + mt * 16 + g;
            int c = bcol + wn * 32 + nt * 8 + tg * 2;
            float bx = 0.f, by = 0.f;
            if (bias) { bx = bias[c]; by = bias[c + 1]; }
            float2 v0 = make_float2(acc[mt][nt][0] + bx, acc[mt][nt][1] + by);
            float2 v1 = make_float2(acc[mt][nt][2] + bx, acc[mt][nt][3] + by);
            if (half_out) {
                __half* Ch = reinterpret_cast<__half*>(C);
                if (r < M)
                    *reinterpret_cast<__half2*>(Ch + (long)r * Nn + c) = __float22half2_rn(v0);
                if (r + 8 < M)
                    *reinterpret_cast<__half2*>(Ch + (long)(r + 8) * Nn + c) = __float22half2_rn(v1);
            } else {
                if (r < M)
                    *reinterpret_cast<float2*>(C + (long)r * Nn + c) = v0;
                if (r + 8 < M)
                    *reinterpret_cast<float2*>(C + (long)(r + 8) * Nn + c) = v1;
            }
        }
    }
}

// ---------------- fold attention vectors into W (both layers, one launch) ---
__global__ void foldw2_k(const float* __restrict__ W1, const float* __restrict__ as1,
                         const float* __restrict__ ad1, float* __restrict__ wsd1,
                         const float* __restrict__ W2, const float* __restrict__ as2,
                         const float* __restrict__ ad2, float* __restrict__ wsd2) {
    int layer = blockIdx.y;
    const float* W   = layer ? W2  : W1;
    const float* as_ = layer ? as2 : as1;
    const float* ad_ = layer ? ad2 : ad1;
    float* wsd = layer ? wsd2 : wsd1;
    int K = layer ? HID : INC;
    int t = blockIdx.x * blockDim.x + threadIdx.x;
    if (t >= K * 8) return;
    int k = t >> 3, j = t & 7, h = j & 3;
    const float* a = ((j < 4) ? as_ : ad_) + h * HID;
    const float* wr = W + (long)k * HH + h * HID;
    float s = 0.f;
    #pragma unroll 16
    for (int c = 0; c < HID; c++) s += wr[c] * a[c];
    wsd[k * 8 + j] = s;
}

// ---------------- skinny scores: es/ed[n][h] = X[n,:] @ Wsd[:,j] ------------
__global__ void sscore_k(const float* __restrict__ X, const float* __restrict__ wsd,
                         float* __restrict__ es, float* __restrict__ ed,
                         int Nn, int K) {
    __shared__ float sW[8][128];
    int tid = threadIdx.x;
    for (int idx = tid; idx < K * 8; idx += blockDim.x) {
        int k = idx >> 3, j = idx & 7;
        sW[j][k] = wsd[k * 8 + j];
    }
    __syncthreads();

    int node = blockIdx.x * 8 + (tid >> 5);
    int lane = tid & 31;
    if (node >= Nn) return;
    int nq = K >> 2;

    float4 xv = make_float4(0.f, 0.f, 0.f, 0.f);
    if (lane < nq)
        xv = reinterpret_cast<const float4*>(X + (long)node * K)[lane];

    float acc[8];
    #pragma unroll
    for (int j = 0; j < 8; j++) {
        float4 wv = make_float4(0.f, 0.f, 0.f, 0.f);
        if (lane < nq)
            wv = *reinterpret_cast<const float4*>(&sW[j][lane * 4]);
        acc[j] = xv.x * wv.x + xv.y * wv.y + xv.z * wv.z + xv.w * wv.w;
    }
    #pragma unroll
    for (int o = 16; o > 0; o >>= 1) {
        #pragma unroll
        for (int j = 0; j < 8; j++)
            acc[j] += __shfl_xor_sync(0xffffffffu, acc[j], o);
    }
    if (lane == 0) {
        *reinterpret_cast<float4*>(es + node * 4) = make_float4(acc[0], acc[1], acc[2], acc[3]);
        *reinterpret_cast<float4*>(ed + node * 4) = make_float4(acc[4], acc[5], acc[6], acc[7]);
    }
}

// ---------------- CSR build ----------------
__global__ void zero2_k(int* __restrict__ a, int* __restrict__ b, int n) {
    int i = blockIdx.x * blockDim.x + threadIdx.x;
    if (i < n) { a[i] = 0; b[i] = 0; }
}

__global__ void deg_k(const int* __restrict__ ei, int* __restrict__ deg,
                      int Ein, int Etot) {
    int e = blockIdx.x * blockDim.x + threadIdx.x;
    if (e >= Etot) return;
    int d = (e < Ein) ? ei[Ein + e] : e - Ein;
    atomicAdd(&deg[d], 1);
}

__global__ void chunksum_k(const int* __restrict__ deg, int* __restrict__ csum, int Nn) {
    __shared__ int wsum[32];
    int t = threadIdx.x, lane = t & 31, wid = t >> 5;
    int i = blockIdx.x * 1024 + t;
    int v = (i < Nn) ? deg[i] : 0;
    #pragma unroll
    for (int o = 16; o > 0; o >>= 1) v += __shfl_xor_sync(0xffffffffu, v, o);
    if (lane == 0) wsum[wid] = v;
    __syncthreads();
    if (wid == 0) {
        int s = wsum[lane];
        #pragma unroll
        for (int o = 16; o > 0; o >>= 1) s += __shfl_xor_sync(0xffffffffu, s, o);
        if (lane == 0) csum[blockIdx.x] = s;
    }
}

// rowptr with inlined chunk-offset reduction (csum holds RAW chunk sums).
// Each block reduces csum[0..blockIdx) itself; last block writes rowptr[Nn].
__global__ void rowptr_k(const int* __restrict__ deg, const int* __restrict__ csum,
                         int* __restrict__ rowptr, int Nn, int nchunk) {
    __shared__ int wsum[32];
    __shared__ int chunk_off;
    int t = threadIdx.x, lane = t & 31, wid = t >> 5;

    if (wid == 0) {
        int v = 0;
        for (int i = lane; i < blockIdx.x; i += 32) v += csum[i];
        #pragma unroll
        for (int o = 16; o > 0; o >>= 1) v += __shfl_xor_sync(0xffffffffu, v, o);
        if (lane == 0) chunk_off = v;
        if (blockIdx.x == nchunk - 1) {
            int tot = 0;
            for (int i = lane; i < nchunk; i += 32) tot += csum[i];
            #pragma unroll
            for (int o = 16; o > 0; o >>= 1) tot += __shfl_xor_sync(0xffffffffu, tot, o);
            if (lane == 0) rowptr[Nn] = tot;
        }
    }

    int i = blockIdx.x * 1024 + t;
    int v = (i < Nn) ? deg[i] : 0;
    int x = v;
    #pragma unroll
    for (int o = 1; o < 32; o <<= 1) {
        int y = __shfl_up_sync(0xffffffffu, x, o);
        if (lane >= o) x += y;
    }
    if (lane == 31) wsum[wid] = x;
    __syncthreads();
    if (wid == 0) {
        int s = wsum[lane];
        #pragma unroll
        for (int o = 1; o < 32; o <<= 1) {
            int y = __shfl_up_sync(0xffffffffu, s, o);
            if (lane >= o) s += y;
        }
        wsum[lane] = s;
    }
    __syncthreads();
    int off = chunk_off + (wid > 0 ? wsum[wid - 1] : 0);
    if (i < Nn) rowptr[i] = off + x - v;
}

__global__ void fill_k(const int* __restrict__ ei, int* __restrict__ cursor,
                       const int* __restrict__ rowptr, int* __restrict__ colsrc,
                       int* __restrict__ coldst, int Ein, int Etot) {
    int e = blockIdx.x * blockDim.x + threadIdx.x;
    if (e >= Etot) return;
    int s, d;
    if (e < Ein) { s = ei[e]; d = ei[Ein + e]; }
    else         { s = d = e - Ein; }
    int p = atomicAdd(&cursor[d], 1);
    int slot = rowptr[d] + p;
    colsrc[slot] = s;
    coldst[slot] = d;
}

// ---------------- per-edge softmax weights (fp16, CSR order) ----------------
__global__ void edgew_k(const int* __restrict__ colsrc, const int* __restrict__ coldst,
                        const float* __restrict__ es, const float* __restrict__ ed,
                        __half* __restrict__ w4, int Etot) {
    int e = blockIdx.x * blockDim.x + threadIdx.x;
    if (e >= Etot) return;
    int s = colsrc[e], d = coldst[e];
    float4 a = *reinterpret_cast<const float4*>(es + (long)s * 4);
    float4 c = *reinterpret_cast<const float4*>(ed + (long)d * 4);
    float4 r;
    float v;
    v = a.x + c.x; v = (v > 0.f) ? v : 0.2f * v; r.x = __expf(v);
    v = a.y + c.y; v = (v > 0.f) ? v : 0.2f * v; r.y = __expf(v);
    v = a.z + c.z; v = (v > 0.f) ? v : 0.2f * v; r.z = __expf(v);
    v = a.w + c.w; v = (v > 0.f) ? v : 0.2f * v; r.w = __expf(v);
    union { __half2 h[2]; uint2 u; } cv;
    cv.h[0] = __float22half2_rn(make_float2(r.x, r.y));
    cv.h[1] = __float22half2_rn(make_float2(r.z, r.w));
    *reinterpret_cast<uint2*>(w4 + (long)e * 4) = cv.u;
}

// ---------------- fused gather (fp16 H, fp16 weights; lean registers) -------
__global__ void gather_k(const __half* __restrict__ H, const int* __restrict__ rowptr,
                         const int* __restrict__ colsrc, const __half* __restrict__ w4,
                         const float* __restrict__ b, const float* __restrict__ g,
                         const float* __restrict__ be,
                         float* __restrict__ out, int Nn) {
    int warp = (blockIdx.x * blockDim.x + threadIdx.x) >> 5;
    int lane = threadIdx.x & 31;
    if (warp >= Nn) return;
    const int head = lane >> 3;

    float acc[8] = {0.f,0.f,0.f,0.f,0.f,0.f,0.f,0.f};
    float den = 0.f;

    int beg = rowptr[warp], end = rowptr[warp + 1];
    const uint4* __restrict__ H4 = reinterpret_cast<const uint4*>(H);

    int e = beg;
    for (; e + 8 <= end; e += 8) {
        int s[8]; float wv[8];
        #pragma unroll
        for (int u = 0; u < 8; u++) {
            s[u]  = colsrc[e + u];
            wv[u] = __half2float(w4[(long)(e + u) * 4 + head]);
        }
        #pragma unroll
        for (int u = 0; u < 8; u++) {
            uint4 hv = H4[(long)s[u] * 32 + lane];
            const __half2* hp = reinterpret_cast<const __half2*>(&hv);
            float2 f0 = __half22float2(hp[0]);
            float2 f1 = __half22float2(hp[1]);
            float2 f2 = __half22float2(hp[2]);
            float2 f3 = __half22float2(hp[3]);
            den += wv[u];
            acc[0] += wv[u] * f0.x; acc[1] += wv[u] * f0.y;
            acc[2] += wv[u] * f1.x; acc[3] += wv[u] * f1.y;
            acc[4] += wv[u] * f2.x; acc[5] += wv[u] * f2.y;
            acc[6] += wv[u] * f3.x; acc[7] += wv[u] * f3.y;
        }
    }
    for (; e < end; e++) {
        int s0  = colsrc[e];
        float w0 = __half2float(w4[(long)e * 4 + head]);
        uint4 hv = H4[(long)s0 * 32 + lane];
        const __half2* hp = reinterpret_cast<const __half2*>(&hv);
        float2 f0 = __half22float2(hp[0]);
        float2 f1 = __half22float2(hp[1]);
        float2 f2 = __half22float2(hp[2]);
        float2 f3 = __half22float2(hp[3]);
        den += w0;
        acc[0] += w0 * f0.x; acc[1] += w0 * f0.y;
        acc[2] += w0 * f1.x; acc[3] += w0 * f1.y;
        acc[4] += w0 * f2.x; acc[5] += w0 * f2.y;
        acc[6] += w0 * f3.x; acc[7] += w0 * f3.y;
    }

    float r = 1.f / den;     // den = full per-head denominator (broadcast weights)
    float v8[8];
    #pragma unroll
    for (int i = 0; i < 8; i++) v8[i] = acc[i] * r;

    // cross-head sum: lanes L, L^8, L^16, L^24 hold same channels, diff heads
    #pragma unroll
    for (int i = 0; i < 8; i++) {
        v8[i] += __shfl_xor_sync(0xffffffffu, v8[i], 8);
        v8[i] += __shfl_xor_sync(0xffffffffu, v8[i], 16);
    }

    int ch = (lane & 7) * 8;
    #pragma unroll
    for (int i = 0; i < 8; i++) v8[i] = v8[i] * 0.25f + b[ch + i];

    float sum = 0.f, ssq = 0.f;
    #pragma unroll
    for (int i = 0; i < 8; i++) { sum += v8[i]; ssq += v8[i] * v8[i]; }
    #pragma unroll
    for (int o = 16; o > 0; o >>= 1) {
        sum += __shfl_xor_sync(0xffffffffu, sum, o);
        ssq += __shfl_xor_sync(0xffffffffu, ssq, o);
    }
    float mean = sum * (1.f / 256.f);
    float var  = ssq * (1.f / 256.f) - mean * mean;
    float inv  = rsqrtf(var + 1e-5f);

    #pragma unroll
    for (int i = 0; i < 8; i++)
        v8[i] = fmaxf((v8[i] - mean) * inv * g[ch + i] + be[ch + i], 0.f);

    if (lane < 8) {
        float4 o0 = make_float4(v8[0], v8[1], v8[2], v8[3]);
        float4 o1 = make_float4(v8[4], v8[5], v8[6], v8[7]);
        float4* op = reinterpret_cast<float4*>(out + (long)warp * HID + ch);
        op[0] = o0; op[1] = o1;
    }
}

// ---------------------------------------------------------------------------
extern "C" void kernel_launch(void* const* d_in, const int* in_sizes, int n_in,
                              void* d_out, int out_size) {
    const float* x     = (const float*)d_in[0];
    const int*   ei    = (const int*)  d_in[1];
    const float* W1    = (const float*)d_in[2];
    const float* asrc1 = (const float*)d_in[3];
    const float* adst1 = (const float*)d_in[4];
    const float* b1    = (const float*)d_in[5];
    const float* g1    = (const float*)d_in[6];
    const float* be1   = (const float*)d_in[7];
    const float* W2    = (const float*)d_in[8];
    const float* asrc2 = (const float*)d_in[9];
    const float* adst2 = (const float*)d_in[10];
    const float* b2    = (const float*)d_in[11];
    const float* g2    = (const float*)d_in[12];
    const float* be2   = (const float*)d_in[13];
    const float* Wo    = (const float*)d_in[14];
    const float* bo    = (const float*)d_in[15];
    float* out = (float*)d_out;

    const int Nn   = in_sizes[0] / INC;      // 50000
    const int Ein  = in_sizes[1] / 2;        // 800000
    const int Etot = Ein + Nn;               // 850000
    const int nchunk = (Nn + 1023) / 1024;

    __half *H, *W4;
    float *ES, *ED, *F1, *F2, *WSD1, *WSD2;
    int *DEG, *CUR, *ROW, *COL, *CDST, *CSUM;
    cudaGetSymbolAddress((void**)&H,    g_H);
    cudaGetSymbolAddress((void**)&ES,   g_ES);
    cudaGetSymbolAddress((void**)&ED,   g_ED);
    cudaGetSymbolAddress((void**)&F1,   g_F1);
    cudaGetSymbolAddress((void**)&F2,   g_F2);
    cudaGetSymbolAddress((void**)&WSD1, g_WSD1);
    cudaGetSymbolAddress((void**)&WSD2, g_WSD2);
    cudaGetSymbolAddress((void**)&W4,   g_W4);
    cudaGetSymbolAddress((void**)&DEG,  g_DEG);
    cudaGetSymbolAddress((void**)&CUR,  g_CUR);
    cudaGetSymbolAddress((void**)&ROW,  g_ROW);
    cudaGetSymbolAddress((void**)&COL,  g_COL);
    cudaGetSymbolAddress((void**)&CDST, g_CDST);
    cudaGetSymbolAddress((void**)&CSUM, g_CSUM);

    dim3 gemm1_grid(HH / 128, (Nn + 127) / 128);
    dim3 gemm2_grid(HH / 128, (Nn + 127) / 128);
    dim3 gemmo_grid(OUTC / 128, (Nn + 127) / 128);
    int edge_blocks  = (Etot + 255) / 256;
    int node_warpblk = (Nn * 32 + 255) / 256;
    int score_blocks = (Nn + 7) / 8;
    dim3 fold_grid((INC * 8 + 255) / 256, 2);

    // ---------------- CSR build + weight folds ----------------
    zero2_k<<<(Nn + 1023) / 1024, 1024>>>(DEG, CUR, Nn);
    deg_k<<<edge_blocks, 256>>>(ei, DEG, Ein, Etot);
    chunksum_k<<<nchunk, 1024>>>(DEG, CSUM, Nn);
    rowptr_k<<<nchunk, 1024>>>(DEG, CSUM, ROW, Nn, nchunk);
    fill_k<<<edge_blocks, 256>>>(ei, CUR, ROW, COL, CDST, Ein, Etot);
    foldw2_k<<<fold_grid, 256>>>(W1, asrc1, adst1, WSD1, W2, asrc2, adst2, WSD2);

    // ---------------- layer 1 ----------------
    sscore_k<<<score_blocks, 256>>>(x, WSD1, ES, ED, Nn, INC);
    tgemm128<<<gemm1_grid, 256>>>(x, W1, (float*)H, Nn, HH, INC, nullptr, 1);
    edgew_k<<<edge_blocks, 256>>>(COL, CDST, ES, ED, W4, Etot);
    gather_k<<<node_warpblk, 256>>>(H, ROW, COL, W4, b1, g1, be1, F1, Nn);

    // ---------------- layer 2 ----------------
    sscore_k<<<score_blocks, 256>>>(F1, WSD2, ES, ED, Nn, HID);
    tgemm128<<<gemm2_grid, 256>>>(F1, W2, (float*)H, Nn, HH, HID, nullptr, 1);
    edgew_k<<<edge_blocks, 256>>>(COL, CDST, ES, ED, W4, Etot);
    gather_k<<<node_warpblk, 256>>>(H, ROW, COL, W4, b2, g2, be2, F2, Nn);

    // ---------------- output projection (fp32 out) ----------------
    tgemm128<<<gemmo_grid, 256>>>(F2, Wo, out, Nn, OUTC, HID, bo, 0);
}

// round 15
// speedup vs baseline: 1.1738x; 1.0618x over previous
#include <cuda_runtime.h>
#include <cuda_fp16.h>
#include <cstdint>

#define NNODES 50000
#define NEDGES 800000
#define ETOT   (NNODES + NEDGES)
#define HEADS  4
#define HID    64
#define HH     256   // HEADS*HID
#define INC    128
#define OUTC   128

// ---------------- scratch (device globals; no allocation) ----------------
__device__ __half g_H [NNODES * HH];      // transformed features, fp16 [N,4,64]
__device__ float g_ES  [NNODES * HEADS];
__device__ float g_ED  [NNODES * HEADS];
__device__ float g_F1  [NNODES * HID];
__device__ float g_F2  [NNODES * HID];
__device__ float g_WSD1[INC * 8];
__device__ float g_WSD2[HID * 8];
__device__ __half g_W4 [(size_t)ETOT * HEADS];   // per-edge weights (fp16), CSR order
__device__ int   g_DEG[NNODES];
__device__ int   g_CUR[NNODES];
__device__ int   g_ROW[NNODES + 1];
__device__ int   g_COL[ETOT];             // src per CSR slot
__device__ int   g_CDST[ETOT];            // dst per CSR slot

// ---------------- helpers ----------------
__device__ __forceinline__ uint32_t f2tf32(float f) {
    uint32_t u;
    asm("cvt.rna.tf32.f32 %0, %1;" : "=r"(u) : "f"(f));
    return u;
}

__device__ __forceinline__ void mma_tf32(float* c, const uint32_t* a, const uint32_t* b) {
    asm volatile(
        "mma.sync.aligned.m16n8k8.row.col.f32.tf32.tf32.f32 "
        "{%0,%1,%2,%3}, {%4,%5,%6,%7}, {%8,%9}, {%0,%1,%2,%3};\n"
        : "+f"(c[0]), "+f"(c[1]), "+f"(c[2]), "+f"(c[3])
        : "r"(a[0]), "r"(a[1]), "r"(a[2]), "r"(a[3]), "r"(b[0]), "r"(b[1]));
}

// ---------------- TF32 tensor-core GEMM, optional fp16 output (R10) ---------
#define ALD 20
#define BLD 136

__global__ __launch_bounds__(256, 2)
void tgemm128(const float* __restrict__ A, const float* __restrict__ B,
              float* __restrict__ C, int M, int Nn, int K,
              const float* __restrict__ bias, int half_out) {
    const int BM = 128, BK = 16;
    __shared__ uint32_t As[2][BM * ALD];
    __shared__ uint32_t Bs[2][BK * BLD];

    int tid  = threadIdx.x;
    int brow = blockIdx.y * BM;
    int bcol = blockIdx.x * 128;
    int w    = tid >> 5, lane = tid & 31;
    int wm   = w & 1, wn = w >> 1;
    int g    = lane >> 2, tg = lane & 3;

    int ar = tid >> 2, ac = (tid & 3) * 4;
    int br = tid >> 5, bc = (tid & 31) * 4;

    const int T = K / BK;
    float acc[4][4][4];
    #pragma unroll
    for (int i = 0; i < 4; i++)
        #pragma unroll
        for (int j = 0; j < 4; j++)
            #pragma unroll
            for (int r = 0; r < 4; r++) acc[i][j][r] = 0.f;

    {
        float4 va0 = make_float4(0.f,0.f,0.f,0.f), va1 = va0;
        long r0 = brow + ar, r1 = brow + ar + 64;
        if (r0 < M) va0 = *reinterpret_cast<const float4*>(A + r0 * K + ac);
        if (r1 < M) va1 = *reinterpret_cast<const float4*>(A + r1 * K + ac);
        uint32_t* d0 = &As[0][ar * ALD + ac];
        d0[0]=f2tf32(va0.x); d0[1]=f2tf32(va0.y); d0[2]=f2tf32(va0.z); d0[3]=f2tf32(va0.w);
        uint32_t* d1 = &As[0][(ar + 64) * ALD + ac];
        d1[0]=f2tf32(va1.x); d1[1]=f2tf32(va1.y); d1[2]=f2tf32(va1.z); d1[3]=f2tf32(va1.w);
        float4 vb0 = *reinterpret_cast<const float4*>(B + (long)br * Nn + bcol + bc);
        float4 vb1 = *reinterpret_cast<const float4*>(B + (long)(br + 8) * Nn + bcol + bc);
        uint32_t* e0 = &Bs[0][br * BLD + bc];
        e0[0]=f2tf32(vb0.x); e0[1]=f2tf32(vb0.y); e0[2]=f2tf32(vb0.z); e0[3]=f2tf32(vb0.w);
        uint32_t* e1 = &Bs[0][(br + 8) * BLD + bc];
        e1[0]=f2tf32(vb1.x); e1[1]=f2tf32(vb1.y); e1[2]=f2tf32(vb1.z); e1[3]=f2tf32(vb1.w);
    }
    __syncthreads();

    for (int t = 0; t < T; t++) {
        int buf = t & 1;
        float4 va0 = make_float4(0.f,0.f,0.f,0.f), va1 = va0, vb0 = va0, vb1 = va0;
        if (t + 1 < T) {
            int k0 = (t + 1) * BK;
            long r0 = brow + ar, r1 = brow + ar + 64;
            if (r0 < M) va0 = *reinterpret_cast<const float4*>(A + r0 * K + k0 + ac);
            if (r1 < M) va1 = *reinterpret_cast<const float4*>(A + r1 * K + k0 + ac);
            vb0 = *reinterpret_cast<const float4*>(B + (long)(k0 + br) * Nn + bcol + bc);
            vb1 = *reinterpret_cast<const float4*>(B + (long)(k0 + br + 8) * Nn + bcol + bc);
        }
        #pragma unroll
        for (int kk = 0; kk < BK; kk += 8) {
            uint32_t af[4][4];
            #pragma unroll
            for (int mt = 0; mt < 4; mt++) {
                int r0 = (wm * 64 + mt * 16 + g) * ALD + kk + tg;
                af[mt][0] = As[buf][r0];
                af[mt][1] = As[buf][r0 + 8 * ALD];
                af[mt][2] = As[buf][r0 + 4];
                af[mt][3] = As[buf][r0 + 8 * ALD + 4];
            }
            uint32_t bf[4][2];
            #pragma unroll
            for (int nt = 0; nt < 4; nt++) {
                int c0 = wn * 32 + nt * 8 + g;
                bf[nt][0] = Bs[buf][(kk + tg) * BLD + c0];
                bf[nt][1] = Bs[buf][(kk + tg + 4) * BLD + c0];
            }
            #pragma unroll
            for (int mt = 0; mt < 4; mt++)
                #pragma unroll
                for (int nt = 0; nt < 4; nt++)
                    mma_tf32(acc[mt][nt], af[mt], bf[nt]);
        }
        if (t + 1 < T) {
            int nb = buf ^ 1;
            uint32_t* d0 = &As[nb][ar * ALD + ac];
            d0[0]=f2tf32(va0.x); d0[1]=f2tf32(va0.y); d0[2]=f2tf32(va0.z); d0[3]=f2tf32(va0.w);
            uint32_t* d1 = &As[nb][(ar + 64) * ALD + ac];
            d1[0]=f2tf32(va1.x); d1[1]=f2tf32(va1.y); d1[2]=f2tf32(va1.z); d1[3]=f2tf32(va1.w);
            uint32_t* e0 = &Bs[nb][br * BLD + bc];
            e0[0]=f2tf32(vb0.x); e0[1]=f2tf32(vb0.y); e0[2]=f2tf32(vb0.z); e0[3]=f2tf32(vb0.w);
            uint32_t* e1 = &Bs[nb][(br + 8) * BLD + bc];
            e1[0]=f2tf32(vb1.x); e1[1]=f2tf32(vb1.y); e1[2]=f2tf32(vb1.z); e1[3]=f2tf32(vb1.w);
            __syncthreads();
        }
    }

    #pragma unroll
    for (int mt = 0; mt < 4; mt++) {
        #pragma unroll
        for (int nt = 0; nt < 4; nt++) {
            int r = brow + wm * 64 + mt * 16 + g;
            int c = bcol + wn * 32 + nt * 8 + tg * 2;
            float bx = 0.f, by = 0.f;
            if (bias) { bx = bias[c]; by = bias[c + 1]; }
            float2 v0 = make_float2(acc[mt][nt][0] + bx, acc[mt][nt][1] + by);
            float2 v1 = make_float2(acc[mt][nt][2] + bx, acc[mt][nt][3] + by);
            if (half_out) {
                __half* Ch = reinterpret_cast<__half*>(C);
                if (r < M)
                    *reinterpret_cast<__half2*>(Ch + (long)r * Nn + c) = __float22half2_rn(v0);
                if (r + 8 < M)
                    *reinterpret_cast<__half2*>(Ch + (long)(r + 8) * Nn + c) = __float22half2_rn(v1);
            } else {
                if (r < M)
                    *reinterpret_cast<float2*>(C + (long)r * Nn + c) = v0;
                if (r + 8 < M)
                    *reinterpret_cast<float2*>(C + (long)(r + 8) * Nn + c) = v1;
            }
        }
    }
}

// ---------------- fold attention vectors into W (both layers, one launch) ---
__global__ void foldw2_k(const float* __restrict__ W1, const float* __restrict__ as1,
                         const float* __restrict__ ad1, float* __restrict__ wsd1,
                         const float* __restrict__ W2, const float* __restrict__ as2,
                         const float* __restrict__ ad2, float* __restrict__ wsd2) {
    int layer = blockIdx.y;
    const float* W   = layer ? W2  : W1;
    const float* as_ = layer ? as2 : as1;
    const float* ad_ = layer ? ad2 : ad1;
    float* wsd = layer ? wsd2 : wsd1;
    int K = layer ? HID : INC;
    int t = blockIdx.x * blockDim.x + threadIdx.x;
    if (t >= K * 8) return;
    int k = t >> 3, j = t & 7, h = j & 3;
    const float* a = ((j < 4) ? as_ : ad_) + h * HID;
    const float* wr = W + (long)k * HH + h * HID;
    float s = 0.f;
    #pragma unroll 16
    for (int c = 0; c < HID; c++) s += wr[c] * a[c];
    wsd[k * 8 + j] = s;
}

// ---------------- skinny scores: es/ed[n][h] = X[n,:] @ Wsd[:,j] ------------
__global__ void sscore_k(const float* __restrict__ X, const float* __restrict__ wsd,
                         float* __restrict__ es, float* __restrict__ ed,
                         int Nn, int K) {
    __shared__ float sW[8][128];
    int tid = threadIdx.x;
    for (int idx = tid; idx < K * 8; idx += blockDim.x) {
        int k = idx >> 3, j = idx & 7;
        sW[j][k] = wsd[k * 8 + j];
    }
    __syncthreads();

    int node = blockIdx.x * 8 + (tid >> 5);
    int lane = tid & 31;
    if (node >= Nn) return;
    int nq = K >> 2;

    float4 xv = make_float4(0.f, 0.f, 0.f, 0.f);
    if (lane < nq)
        xv = reinterpret_cast<const float4*>(X + (long)node * K)[lane];

    float acc[8];
    #pragma unroll
    for (int j = 0; j < 8; j++) {
        float4 wv = make_float4(0.f, 0.f, 0.f, 0.f);
        if (lane < nq)
            wv = *reinterpret_cast<const float4*>(&sW[j][lane * 4]);
        acc[j] = xv.x * wv.x + xv.y * wv.y + xv.z * wv.z + xv.w * wv.w;
    }
    #pragma unroll
    for (int o = 16; o > 0; o >>= 1) {
        #pragma unroll
        for (int j = 0; j < 8; j++)
            acc[j] += __shfl_xor_sync(0xffffffffu, acc[j], o);
    }
    if (lane == 0) {
        *reinterpret_cast<float4*>(es + node * 4) = make_float4(acc[0], acc[1], acc[2], acc[3]);
        *reinterpret_cast<float4*>(ed + node * 4) = make_float4(acc[4], acc[5], acc[6], acc[7]);
    }
}

// ---------------- CSR build ----------------
__global__ void deg_k(const int* __restrict__ ei, int* __restrict__ deg,
                      int Ein, int Etot) {
    int e = blockIdx.x * blockDim.x + threadIdx.x;
    if (e >= Etot) return;
    int d = (e < Ein) ? ei[Ein + e] : e - Ein;
    atomicAdd(&deg[d], 1);
}

// rowptr with self-computed chunk offset (no separate chunksum/scan kernels).
// Also writes cur[i] = rowptr[i] so fill_k needs no rowptr gather.
__global__ void rowptr_k(const int* __restrict__ deg, int* __restrict__ rowptr,
                         int* __restrict__ cur, int Nn, int nchunk) {
    __shared__ int wsum[32];
    __shared__ int chunk_off;
    int t = threadIdx.x, lane = t & 31, wid = t >> 5;
    int base = blockIdx.x * 1024;

    // phase 1: chunk_off = sum(deg[0..base)) via full-block strided reduce
    {
        int v = 0;
        for (int i = t; i < base; i += 1024) v += deg[i];
        #pragma unroll
        for (int o = 16; o > 0; o >>= 1) v += __shfl_xor_sync(0xffffffffu, v, o);
        if (lane == 0) wsum[wid] = v;
        __syncthreads();
        if (wid == 0) {
            int s = wsum[lane];
            #pragma unroll
            for (int o = 16; o > 0; o >>= 1) s += __shfl_xor_sync(0xffffffffu, s, o);
            if (lane == 0) chunk_off = s;
        }
        __syncthreads();
    }

    // phase 2: exclusive scan of own chunk
    int i = base + t;
    int v = (i < Nn) ? deg[i] : 0;
    int x = v;
    #pragma unroll
    for (int o = 1; o < 32; o <<= 1) {
        int y = __shfl_up_sync(0xffffffffu, x, o);
        if (lane >= o) x += y;
    }
    if (lane == 31) wsum[wid] = x;
    __syncthreads();
    if (wid == 0) {
        int s = wsum[lane];
        #pragma unroll
        for (int o = 1; o < 32; o <<= 1) {
            int y = __shfl_up_sync(0xffffffffu, s, o);
            if (lane >= o) s += y;
        }
        wsum[lane] = s;
    }
    __syncthreads();
    int off = chunk_off + (wid > 0 ? wsum[wid - 1] : 0);
    if (i < Nn) {
        int rp = off + x - v;
        rowptr[i] = rp;
        cur[i]    = rp;
    }
    if (blockIdx.x == nchunk - 1 && t == 0)
        rowptr[Nn] = chunk_off + wsum[31];
}

__global__ void fill_k(const int* __restrict__ ei, int* __restrict__ cursor,
                       int* __restrict__ colsrc, int* __restrict__ coldst,
                       int Ein, int Etot) {
    int e = blockIdx.x * blockDim.x + threadIdx.x;
    if (e >= Etot) return;
    int s, d;
    if (e < Ein) { s = ei[e]; d = ei[Ein + e]; }
    else         { s = d = e - Ein; }
    int slot = atomicAdd(&cursor[d], 1);
    colsrc[slot] = s;
    coldst[slot] = d;
}

// ---------------- per-edge softmax weights (fp16, CSR order) ----------------
__global__ void edgew_k(const int* __restrict__ colsrc, const int* __restrict__ coldst,
                        const float* __restrict__ es, const float* __restrict__ ed,
                        __half* __restrict__ w4, int Etot) {
    int e = blockIdx.x * blockDim.x + threadIdx.x;
    if (e >= Etot) return;
    int s = colsrc[e], d = coldst[e];
    float4 a = *reinterpret_cast<const float4*>(es + (long)s * 4);
    float4 c = *reinterpret_cast<const float4*>(ed + (long)d * 4);
    float4 r;
    float v;
    v = a.x + c.x; v = (v > 0.f) ? v : 0.2f * v; r.x = __expf(v);
    v = a.y + c.y; v = (v > 0.f) ? v : 0.2f * v; r.y = __expf(v);
    v = a.z + c.z; v = (v > 0.f) ? v : 0.2f * v; r.z = __expf(v);
    v = a.w + c.w; v = (v > 0.f) ? v : 0.2f * v; r.w = __expf(v);
    union { __half2 h[2]; uint2 u; } cv;
    cv.h[0] = __float22half2_rn(make_float2(r.x, r.y));
    cv.h[1] = __float22half2_rn(make_float2(r.z, r.w));
    *reinterpret_cast<uint2*>(w4 + (long)e * 4) = cv.u;
}

// ---------------- fused gather (fp16 H, fp16 weights; lean registers) -------
__global__ void gather_k(const __half* __restrict__ H, const int* __restrict__ rowptr,
                         const int* __restrict__ colsrc, const __half* __restrict__ w4,
                         const float* __restrict__ b, const float* __restrict__ g,
                         const float* __restrict__ be,
                         float* __restrict__ out, int Nn) {
    int warp = (blockIdx.x * blockDim.x + threadIdx.x) >> 5;
    int lane = threadIdx.x & 31;
    if (warp >= Nn) return;
    const int head = lane >> 3;

    float acc[8] = {0.f,0.f,0.f,0.f,0.f,0.f,0.f,0.f};
    float den = 0.f;

    int beg = rowptr[warp], end = rowptr[warp + 1];
    const uint4* __restrict__ H4 = reinterpret_cast<const uint4*>(H);

    int e = beg;
    for (; e + 8 <= end; e += 8) {
        int s[8]; float wv[8];
        #pragma unroll
        for (int u = 0; u < 8; u++) {
            s[u]  = colsrc[e + u];
            wv[u] = __half2float(w4[(long)(e + u) * 4 + head]);
        }
        #pragma unroll
        for (int u = 0; u < 8; u++) {
            uint4 hv = H4[(long)s[u] * 32 + lane];
            const __half2* hp = reinterpret_cast<const __half2*>(&hv);
            float2 f0 = __half22float2(hp[0]);
            float2 f1 = __half22float2(hp[1]);
            float2 f2 = __half22float2(hp[2]);
            float2 f3 = __half22float2(hp[3]);
            den += wv[u];
            acc[0] += wv[u] * f0.x; acc[1] += wv[u] * f0.y;
            acc[2] += wv[u] * f1.x; acc[3] += wv[u] * f1.y;
            acc[4] += wv[u] * f2.x; acc[5] += wv[u] * f2.y;
            acc[6] += wv[u] * f3.x; acc[7] += wv[u] * f3.y;
        }
    }
    for (; e < end; e++) {
        int s0  = colsrc[e];
        float w0 = __half2float(w4[(long)e * 4 + head]);
        uint4 hv = H4[(long)s0 * 32 + lane];
        const __half2* hp = reinterpret_cast<const __half2*>(&hv);
        float2 f0 = __half22float2(hp[0]);
        float2 f1 = __half22float2(hp[1]);
        float2 f2 = __half22float2(hp[2]);
        float2 f3 = __half22float2(hp[3]);
        den += w0;
        acc[0] += w0 * f0.x; acc[1] += w0 * f0.y;
        acc[2] += w0 * f1.x; acc[3] += w0 * f1.y;
        acc[4] += w0 * f2.x; acc[5] += w0 * f2.y;
        acc[6] += w0 * f3.x; acc[7] += w0 * f3.y;
    }

    float r = 1.f / den;
    float v8[8];
    #pragma unroll
    for (int i = 0; i < 8; i++) v8[i] = acc[i] * r;

    #pragma unroll
    for (int i = 0; i < 8; i++) {
        v8[i] += __shfl_xor_sync(0xffffffffu, v8[i], 8);
        v8[i] += __shfl_xor_sync(0xffffffffu, v8[i], 16);
    }

    int ch = (lane & 7) * 8;
    #pragma unroll
    for (int i = 0; i < 8; i++) v8[i] = v8[i] * 0.25f + b[ch + i];

    float sum = 0.f, ssq = 0.f;
    #pragma unroll
    for (int i = 0; i < 8; i++) { sum += v8[i]; ssq += v8[i] * v8[i]; }
    #pragma unroll
    for (int o = 16; o > 0; o >>= 1) {
        sum += __shfl_xor_sync(0xffffffffu, sum, o);
        ssq += __shfl_xor_sync(0xffffffffu, ssq, o);
    }
    float mean = sum * (1.f / 256.f);
    float var  = ssq * (1.f / 256.f) - mean * mean;
    float inv  = rsqrtf(var + 1e-5f);

    #pragma unroll
    for (int i = 0; i < 8; i++)
        v8[i] = fmaxf((v8[i] - mean) * inv * g[ch + i] + be[ch + i], 0.f);

    if (lane < 8) {
        float4 o0 = make_float4(v8[0], v8[1], v8[2], v8[3]);
        float4 o1 = make_float4(v8[4], v8[5], v8[6], v8[7]);
        float4* op = reinterpret_cast<float4*>(out + (long)warp * HID + ch);
        op[0] = o0; op[1] = o1;
    }
}

// ---------------------------------------------------------------------------
extern "C" void kernel_launch(void* const* d_in, const int* in_sizes, int n_in,
                              void* d_out, int out_size) {
    const float* x     = (const float*)d_in[0];
    const int*   ei    = (const int*)  d_in[1];
    const float* W1    = (const float*)d_in[2];
    const float* asrc1 = (const float*)d_in[3];
    const float* adst1 = (const float*)d_in[4];
    const float* b1    = (const float*)d_in[5];
    const float* g1    = (const float*)d_in[6];
    const float* be1   = (const float*)d_in[7];
    const float* W2    = (const float*)d_in[8];
    const float* asrc2 = (const float*)d_in[9];
    const float* adst2 = (const float*)d_in[10];
    const float* b2    = (const float*)d_in[11];
    const float* g2    = (const float*)d_in[12];
    const float* be2   = (const float*)d_in[13];
    const float* Wo    = (const float*)d_in[14];
    const float* bo    = (const float*)d_in[15];
    float* out = (float*)d_out;

    const int Nn   = in_sizes[0] / INC;      // 50000
    const int Ein  = in_sizes[1] / 2;        // 800000
    const int Etot = Ein + Nn;               // 850000
    const int nchunk = (Nn + 1023) / 1024;

    __half *H, *W4;
    float *ES, *ED, *F1, *F2, *WSD1, *WSD2;
    int *DEG, *CUR, *ROW, *COL, *CDST;
    cudaGetSymbolAddress((void**)&H,    g_H);
    cudaGetSymbolAddress((void**)&ES,   g_ES);
    cudaGetSymbolAddress((void**)&ED,   g_ED);
    cudaGetSymbolAddress((void**)&F1,   g_F1);
    cudaGetSymbolAddress((void**)&F2,   g_F2);
    cudaGetSymbolAddress((void**)&WSD1, g_WSD1);
    cudaGetSymbolAddress((void**)&WSD2, g_WSD2);
    cudaGetSymbolAddress((void**)&W4,   g_W4);
    cudaGetSymbolAddress((void**)&DEG,  g_DEG);
    cudaGetSymbolAddress((void**)&CUR,  g_CUR);
    cudaGetSymbolAddress((void**)&ROW,  g_ROW);
    cudaGetSymbolAddress((void**)&COL,  g_COL);
    cudaGetSymbolAddress((void**)&CDST, g_CDST);

    // lazy side stream + events (created on first, uncaptured, call)
    static cudaStream_t s1 = nullptr;
    static cudaEvent_t ev0 = nullptr, ev1, ev2, ev3;
    if (!s1) {
        cudaStreamCreateWithFlags(&s1, cudaStreamNonBlocking);
        cudaEventCreateWithFlags(&ev0, cudaEventDisableTiming);
        cudaEventCreateWithFlags(&ev1, cudaEventDisableTiming);
        cudaEventCreateWithFlags(&ev2, cudaEventDisableTiming);
        cudaEventCreateWithFlags(&ev3, cudaEventDisableTiming);
    }

    dim3 gemm1_grid(HH / 128, (Nn + 127) / 128);
    dim3 gemm2_grid(HH / 128, (Nn + 127) / 128);
    dim3 gemmo_grid(OUTC / 128, (Nn + 127) / 128);
    int edge_blocks  = (Etot + 255) / 256;
    int node_warpblk = (Nn * 32 + 255) / 256;
    int score_blocks = (Nn + 7) / 8;
    dim3 fold_grid((INC * 8 + 255) / 256, 2);

    // ---------------- CSR build + weight folds (main stream) ----------------
    cudaMemsetAsync(DEG, 0, (size_t)Nn * sizeof(int), 0);
    deg_k<<<edge_blocks, 256>>>(ei, DEG, Ein, Etot);
    rowptr_k<<<nchunk, 1024>>>(DEG, ROW, CUR, Nn, nchunk);
    fill_k<<<edge_blocks, 256>>>(ei, CUR, COL, CDST, Ein, Etot);
    foldw2_k<<<fold_grid, 256>>>(W1, asrc1, adst1, WSD1, W2, asrc2, adst2, WSD2);

    // ---------------- layer 1: side = sscore1+edgew1 || main = gemm1 --------
    cudaEventRecord(ev0, 0);
    cudaStreamWaitEvent(s1, ev0, 0);
    sscore_k<<<score_blocks, 256, 0, s1>>>(x, WSD1, ES, ED, Nn, INC);
    edgew_k<<<edge_blocks, 256, 0, s1>>>(COL, CDST, ES, ED, W4, Etot);
    cudaEventRecord(ev1, s1);

    tgemm128<<<gemm1_grid, 256>>>(x, W1, (float*)H, Nn, HH, INC, nullptr, 1);
    cudaStreamWaitEvent(0, ev1, 0);
    gather_k<<<node_warpblk, 256>>>(H, ROW, COL, W4, b1, g1, be1, F1, Nn);

    // ---------------- layer 2: side = sscore2+edgew2 || main = gemm2 --------
    cudaEventRecord(ev2, 0);
    cudaStreamWaitEvent(s1, ev2, 0);
    sscore_k<<<score_blocks, 256, 0, s1>>>(F1, WSD2, ES, ED, Nn, HID);
    edgew_k<<<edge_blocks, 256, 0, s1>>>(COL, CDST, ES, ED, W4, Etot);
    cudaEventRecord(ev3, s1);

    tgemm128<<<gemm2_grid, 256>>>(F1, W2, (float*)H, Nn, HH, HID, nullptr, 1);
    cudaStreamWaitEvent(0, ev3, 0);
    gather_k<<<node_warpblk, 256>>>(H, ROW, COL, W4, b2, g2, be2, F2, Nn);

    // ---------------- output projection (fp32 out) ----------------
    tgemm128<<<gemmo_grid, 256>>>(F2, Wo, out, Nn, OUTC, HID, bo, 0);
}

// round 16
// speedup vs baseline: 1.2116x; 1.0322x over previous
#include <cuda_runtime.h>
#include <cuda_fp16.h>
#include <cstdint>

#define NNODES 50000
#define NEDGES 800000
#define ETOT   (NNODES + NEDGES)
#define HEADS  4
#define HID    64
#define HH     256   // HEADS*HID
#define INC    128
#define OUTC   128

// ---------------- scratch (device globals; no allocation) ----------------
__device__ __half g_H [NNODES * HH];      // transformed features, fp16 [N,4,64]
__device__ float g_ES  [NNODES * HEADS];
__device__ float g_ED  [NNODES * HEADS];
__device__ float g_F1  [NNODES * HID];
__device__ float g_F2  [NNODES * HID];
__device__ float g_WSD1[INC * 8];
__device__ float g_WSD2[HID * 8];
__device__ __half g_W4 [(size_t)ETOT * HEADS];   // per-edge weights (fp16), CSR order
__device__ int   g_DEG[NNODES];
__device__ int   g_CUR[NNODES];
__device__ int   g_ROW[NNODES + 1];
__device__ int   g_COL[ETOT];             // src per CSR slot
__device__ int   g_CDST[ETOT];            // dst per CSR slot

// ---------------- helpers ----------------
__device__ __forceinline__ uint32_t f2tf32(float f) {
    uint32_t u;
    asm("cvt.rna.tf32.f32 %0, %1;" : "=r"(u) : "f"(f));
    return u;
}

__device__ __forceinline__ void mma_tf32(float* c, const uint32_t* a, const uint32_t* b) {
    asm volatile(
        "mma.sync.aligned.m16n8k8.row.col.f32.tf32.tf32.f32 "
        "{%0,%1,%2,%3}, {%4,%5,%6,%7}, {%8,%9}, {%0,%1,%2,%3};\n"
        : "+f"(c[0]), "+f"(c[1]), "+f"(c[2]), "+f"(c[3])
        : "r"(a[0]), "r"(a[1]), "r"(a[2]), "r"(a[3]), "r"(b[0]), "r"(b[1]));
}

// ---------------- TF32 tensor-core GEMM, optional fp16 output (R10) ---------
#define ALD 20
#define BLD 136

__global__ __launch_bounds__(256, 2)
void tgemm128(const float* __restrict__ A, const float* __restrict__ B,
              float* __restrict__ C, int M, int Nn, int K,
              const float* __restrict__ bias, int half_out) {
    const int BM = 128, BK = 16;
    __shared__ uint32_t As[2][BM * ALD];
    __shared__ uint32_t Bs[2][BK * BLD];

    int tid  = threadIdx.x;
    int brow = blockIdx.y * BM;
    int bcol = blockIdx.x * 128;
    int w    = tid >> 5, lane = tid & 31;
    int wm   = w & 1, wn = w >> 1;
    int g    = lane >> 2, tg = lane & 3;

    int ar = tid >> 2, ac = (tid & 3) * 4;
    int br = tid >> 5, bc = (tid & 31) * 4;

    const int T = K / BK;
    float acc[4][4][4];
    #pragma unroll
    for (int i = 0; i < 4; i++)
        #pragma unroll
        for (int j = 0; j < 4; j++)
            #pragma unroll
            for (int r = 0; r < 4; r++) acc[i][j][r] = 0.f;

    {
        float4 va0 = make_float4(0.f,0.f,0.f,0.f), va1 = va0;
        long r0 = brow + ar, r1 = brow + ar + 64;
        if (r0 < M) va0 = *reinterpret_cast<const float4*>(A + r0 * K + ac);
        if (r1 < M) va1 = *reinterpret_cast<const float4*>(A + r1 * K + ac);
        uint32_t* d0 = &As[0][ar * ALD + ac];
        d0[0]=f2tf32(va0.x); d0[1]=f2tf32(va0.y); d0[2]=f2tf32(va0.z); d0[3]=f2tf32(va0.w);
        uint32_t* d1 = &As[0][(ar + 64) * ALD + ac];
        d1[0]=f2tf32(va1.x); d1[1]=f2tf32(va1.y); d1[2]=f2tf32(va1.z); d1[3]=f2tf32(va1.w);
        float4 vb0 = *reinterpret_cast<const float4*>(B + (long)br * Nn + bcol + bc);
        float4 vb1 = *reinterpret_cast<const float4*>(B + (long)(br + 8) * Nn + bcol + bc);
        uint32_t* e0 = &Bs[0][br * BLD + bc];
        e0[0]=f2tf32(vb0.x); e0[1]=f2tf32(vb0.y); e0[2]=f2tf32(vb0.z); e0[3]=f2tf32(vb0.w);
        uint32_t* e1 = &Bs[0][(br + 8) * BLD + bc];
        e1[0]=f2tf32(vb1.x); e1[1]=f2tf32(vb1.y); e1[2]=f2tf32(vb1.z); e1[3]=f2tf32(vb1.w);
    }
    __syncthreads();

    for (int t = 0; t < T; t++) {
        int buf = t & 1;
        float4 va0 = make_float4(0.f,0.f,0.f,0.f), va1 = va0, vb0 = va0, vb1 = va0;
        if (t + 1 < T) {
            int k0 = (t + 1) * BK;
            long r0 = brow + ar, r1 = brow + ar + 64;
            if (r0 < M) va0 = *reinterpret_cast<const float4*>(A + r0 * K + k0 + ac);
            if (r1 < M) va1 = *reinterpret_cast<const float4*>(A + r1 * K + k0 + ac);
            vb0 = *reinterpret_cast<const float4*>(B + (long)(k0 + br) * Nn + bcol + bc);
            vb1 = *reinterpret_cast<const float4*>(B + (long)(k0 + br + 8) * Nn + bcol + bc);
        }
        #pragma unroll
        for (int kk = 0; kk < BK; kk += 8) {
            uint32_t af[4][4];
            #pragma unroll
            for (int mt = 0; mt < 4; mt++) {
                int r0 = (wm * 64 + mt * 16 + g) * ALD + kk + tg;
                af[mt][0] = As[buf][r0];
                af[mt][1] = As[buf][r0 + 8 * ALD];
                af[mt][2] = As[buf][r0 + 4];
                af[mt][3] = As[buf][r0 + 8 * ALD + 4];
            }
            uint32_t bf[4][2];
            #pragma unroll
            for (int nt = 0; nt < 4; nt++) {
                int c0 = wn * 32 + nt * 8 + g;
                bf[nt][0] = Bs[buf][(kk + tg) * BLD + c0];
                bf[nt][1] = Bs[buf][(kk + tg + 4) * BLD + c0];
            }
            #pragma unroll
            for (int mt = 0; mt < 4; mt++)
                #pragma unroll
                for (int nt = 0; nt < 4; nt++)
                    mma_tf32(acc[mt][nt], af[mt], bf[nt]);
        }
        if (t + 1 < T) {
            int nb = buf ^ 1;
            uint32_t* d0 = &As[nb][ar * ALD + ac];
            d0[0]=f2tf32(va0.x); d0[1]=f2tf32(va0.y); d0[2]=f2tf32(va0.z); d0[3]=f2tf32(va0.w);
            uint32_t* d1 = &As[nb][(ar + 64) * ALD + ac];
            d1[0]=f2tf32(va1.x); d1[1]=f2tf32(va1.y); d1[2]=f2tf32(va1.z); d1[3]=f2tf32(va1.w);
            uint32_t* e0 = &Bs[nb][br * BLD + bc];
            e0[0]=f2tf32(vb0.x); e0[1]=f2tf32(vb0.y); e0[2]=f2tf32(vb0.z); e0[3]=f2tf32(vb0.w);
            uint32_t* e1 = &Bs[nb][(br + 8) * BLD + bc];
            e1[0]=f2tf32(vb1.x); e1[1]=f2tf32(vb1.y); e1[2]=f2tf32(vb1.z); e1[3]=f2tf32(vb1.w);
            __syncthreads();
        }
    }

    #pragma unroll
    for (int mt = 0; mt < 4; mt++) {
        #pragma unroll
        for (int nt = 0; nt < 4; nt++) {
            int r = brow + wm * 64 + mt * 16 + g;
            int c = bcol + wn * 32 + nt * 8 + tg * 2;
            float bx = 0.f, by = 0.f;
            if (bias) { bx = bias[c]; by = bias[c + 1]; }
            float2 v0 = make_float2(acc[mt][nt][0] + bx, acc[mt][nt][1] + by);
            float2 v1 = make_float2(acc[mt][nt][2] + bx, acc[mt][nt][3] + by);
            if (half_out) {
                __half* Ch = reinterpret_cast<__half*>(C);
                if (r < M)
                    *reinterpret_cast<__half2*>(Ch + (long)r * Nn + c) = __float22half2_rn(v0);
                if (r + 8 < M)
                    *reinterpret_cast<__half2*>(Ch + (long)(r + 8) * Nn + c) = __float22half2_rn(v1);
            } else {
                if (r < M)
                    *reinterpret_cast<float2*>(C + (long)r * Nn + c) = v0;
                if (r + 8 < M)
                    *reinterpret_cast<float2*>(C + (long)(r + 8) * Nn + c) = v1;
            }
        }
    }
}

// ---------------- fold attention vectors into W (warp per output) -----------
__global__ void foldw2_k(const float* __restrict__ W1, const float* __restrict__ as1,
                         const float* __restrict__ ad1, float* __restrict__ wsd1,
                         const float* __restrict__ W2, const float* __restrict__ as2,
                         const float* __restrict__ ad2, float* __restrict__ wsd2) {
    int layer = blockIdx.y;
    const float* W   = layer ? W2  : W1;
    const float* as_ = layer ? as2 : as1;
    const float* ad_ = layer ? ad2 : ad1;
    float* wsd = layer ? wsd2 : wsd1;
    int K = layer ? HID : INC;
    int gw   = blockIdx.x * 8 + (threadIdx.x >> 5);
    int lane = threadIdx.x & 31;
    if (gw >= K * 8) return;
    int k = gw >> 3, j = gw & 7, h = j & 3;
    const float* a  = ((j < 4) ? as_ : ad_) + h * HID;
    const float* wr = W + (long)k * HH + h * HID;
    float s = wr[lane] * a[lane] + wr[lane + 32] * a[lane + 32];
    #pragma unroll
    for (int o = 16; o > 0; o >>= 1)
        s += __shfl_xor_sync(0xffffffffu, s, o);
    if (lane == 0) wsd[gw] = s;
}

// ---------------- skinny scores: es/ed[n][h] = X[n,:] @ Wsd[:,j] ------------
__global__ void sscore_k(const float* __restrict__ X, const float* __restrict__ wsd,
                         float* __restrict__ es, float* __restrict__ ed,
                         int Nn, int K) {
    __shared__ float sW[8][128];
    int tid = threadIdx.x;
    for (int idx = tid; idx < K * 8; idx += blockDim.x) {
        int k = idx >> 3, j = idx & 7;
        sW[j][k] = wsd[k * 8 + j];
    }
    __syncthreads();

    int node = blockIdx.x * 8 + (tid >> 5);
    int lane = tid & 31;
    if (node >= Nn) return;
    int nq = K >> 2;

    float4 xv = make_float4(0.f, 0.f, 0.f, 0.f);
    if (lane < nq)
        xv = reinterpret_cast<const float4*>(X + (long)node * K)[lane];

    float acc[8];
    #pragma unroll
    for (int j = 0; j < 8; j++) {
        float4 wv = make_float4(0.f, 0.f, 0.f, 0.f);
        if (lane < nq)
            wv = *reinterpret_cast<const float4*>(&sW[j][lane * 4]);
        acc[j] = xv.x * wv.x + xv.y * wv.y + xv.z * wv.z + xv.w * wv.w;
    }
    #pragma unroll
    for (int o = 16; o > 0; o >>= 1) {
        #pragma unroll
        for (int j = 0; j < 8; j++)
            acc[j] += __shfl_xor_sync(0xffffffffu, acc[j], o);
    }
    if (lane == 0) {
        *reinterpret_cast<float4*>(es + node * 4) = make_float4(acc[0], acc[1], acc[2], acc[3]);
        *reinterpret_cast<float4*>(ed + node * 4) = make_float4(acc[4], acc[5], acc[6], acc[7]);
    }
}

// ---------------- CSR build ----------------
__global__ void deg_k(const int* __restrict__ ei, int* __restrict__ deg,
                      int Ein, int Etot) {
    int e = blockIdx.x * blockDim.x + threadIdx.x;
    if (e >= Etot) return;
    int d = (e < Ein) ? ei[Ein + e] : e - Ein;
    atomicAdd(&deg[d], 1);
}

// rowptr with self-computed chunk offset; also seeds cur[] = rowptr[].
__global__ void rowptr_k(const int* __restrict__ deg, int* __restrict__ rowptr,
                         int* __restrict__ cur, int Nn, int nchunk) {
    __shared__ int wsum[32];
    __shared__ int chunk_off;
    int t = threadIdx.x, lane = t & 31, wid = t >> 5;
    int base = blockIdx.x * 1024;

    {
        int v = 0;
        for (int i = t; i < base; i += 1024) v += deg[i];
        #pragma unroll
        for (int o = 16; o > 0; o >>= 1) v += __shfl_xor_sync(0xffffffffu, v, o);
        if (lane == 0) wsum[wid] = v;
        __syncthreads();
        if (wid == 0) {
            int s = wsum[lane];
            #pragma unroll
            for (int o = 16; o > 0; o >>= 1) s += __shfl_xor_sync(0xffffffffu, s, o);
            if (lane == 0) chunk_off = s;
        }
        __syncthreads();
    }

    int i = base + t;
    int v = (i < Nn) ? deg[i] : 0;
    int x = v;
    #pragma unroll
    for (int o = 1; o < 32; o <<= 1) {
        int y = __shfl_up_sync(0xffffffffu, x, o);
        if (lane >= o) x += y;
    }
    if (lane == 31) wsum[wid] = x;
    __syncthreads();
    if (wid == 0) {
        int s = wsum[lane];
        #pragma unroll
        for (int o = 1; o < 32; o <<= 1) {
            int y = __shfl_up_sync(0xffffffffu, s, o);
            if (lane >= o) s += y;
        }
        wsum[lane] = s;
    }
    __syncthreads();
    int off = chunk_off + (wid > 0 ? wsum[wid - 1] : 0);
    if (i < Nn) {
        int rp = off + x - v;
        rowptr[i] = rp;
        cur[i]    = rp;
    }
    if (blockIdx.x == nchunk - 1 && t == 0)
        rowptr[Nn] = chunk_off + wsum[31];
}

__global__ void fill_k(const int* __restrict__ ei, int* __restrict__ cursor,
                       int* __restrict__ colsrc, int* __restrict__ coldst,
                       int Ein, int Etot) {
    int e = blockIdx.x * blockDim.x + threadIdx.x;
    if (e >= Etot) return;
    int s, d;
    if (e < Ein) { s = ei[e]; d = ei[Ein + e]; }
    else         { s = d = e - Ein; }
    int slot = atomicAdd(&cursor[d], 1);
    colsrc[slot] = s;
    coldst[slot] = d;
}

// ---------------- per-edge softmax weights (fp16, CSR order) ----------------
__global__ void edgew_k(const int* __restrict__ colsrc, const int* __restrict__ coldst,
                        const float* __restrict__ es, const float* __restrict__ ed,
                        __half* __restrict__ w4, int Etot) {
    int e = blockIdx.x * blockDim.x + threadIdx.x;
    if (e >= Etot) return;
    int s = colsrc[e], d = coldst[e];
    float4 a = *reinterpret_cast<const float4*>(es + (long)s * 4);
    float4 c = *reinterpret_cast<const float4*>(ed + (long)d * 4);
    float4 r;
    float v;
    v = a.x + c.x; v = (v > 0.f) ? v : 0.2f * v; r.x = __expf(v);
    v = a.y + c.y; v = (v > 0.f) ? v : 0.2f * v; r.y = __expf(v);
    v = a.z + c.z; v = (v > 0.f) ? v : 0.2f * v; r.z = __expf(v);
    v = a.w + c.w; v = (v > 0.f) ? v : 0.2f * v; r.w = __expf(v);
    union { __half2 h[2]; uint2 u; } cv;
    cv.h[0] = __float22half2_rn(make_float2(r.x, r.y));
    cv.h[1] = __float22half2_rn(make_float2(r.z, r.w));
    *reinterpret_cast<uint2*>(w4 + (long)e * 4) = cv.u;
}

// ---------------- fused gather (fp16 H, fp16 weights; lean registers) -------
__global__ void gather_k(const __half* __restrict__ H, const int* __restrict__ rowptr,
                         const int* __restrict__ colsrc, const __half* __restrict__ w4,
                         const float* __restrict__ b, const float* __restrict__ g,
                         const float* __restrict__ be,
                         float* __restrict__ out, int Nn) {
    int warp = (blockIdx.x * blockDim.x + threadIdx.x) >> 5;
    int lane = threadIdx.x & 31;
    if (warp >= Nn) return;
    const int head = lane >> 3;

    float acc[8] = {0.f,0.f,0.f,0.f,0.f,0.f,0.f,0.f};
    float den = 0.f;

    int beg = rowptr[warp], end = rowptr[warp + 1];
    const uint4* __restrict__ H4 = reinterpret_cast<const uint4*>(H);

    int e = beg;
    for (; e + 8 <= end; e += 8) {
        int s[8]; float wv[8];
        #pragma unroll
        for (int u = 0; u < 8; u++) {
            s[u]  = colsrc[e + u];
            wv[u] = __half2float(w4[(long)(e + u) * 4 + head]);
        }
        #pragma unroll
        for (int u = 0; u < 8; u++) {
            uint4 hv = H4[(long)s[u] * 32 + lane];
            const __half2* hp = reinterpret_cast<const __half2*>(&hv);
            float2 f0 = __half22float2(hp[0]);
            float2 f1 = __half22float2(hp[1]);
            float2 f2 = __half22float2(hp[2]);
            float2 f3 = __half22float2(hp[3]);
            den += wv[u];
            acc[0] += wv[u] * f0.x; acc[1] += wv[u] * f0.y;
            acc[2] += wv[u] * f1.x; acc[3] += wv[u] * f1.y;
            acc[4] += wv[u] * f2.x; acc[5] += wv[u] * f2.y;
            acc[6] += wv[u] * f3.x; acc[7] += wv[u] * f3.y;
        }
    }
    for (; e < end; e++) {
        int s0  = colsrc[e];
        float w0 = __half2float(w4[(long)e * 4 + head]);
        uint4 hv = H4[(long)s0 * 32 + lane];
        const __half2* hp = reinterpret_cast<const __half2*>(&hv);
        float2 f0 = __half22float2(hp[0]);
        float2 f1 = __half22float2(hp[1]);
        float2 f2 = __half22float2(hp[2]);
        float2 f3 = __half22float2(hp[3]);
        den += w0;
        acc[0] += w0 * f0.x; acc[1] += w0 * f0.y;
        acc[2] += w0 * f1.x; acc[3] += w0 * f1.y;
        acc[4] += w0 * f2.x; acc[5] += w0 * f2.y;
        acc[6] += w0 * f3.x; acc[7] += w0 * f3.y;
    }

    float r = 1.f / den;
    float v8[8];
    #pragma unroll
    for (int i = 0; i < 8; i++) v8[i] = acc[i] * r;

    #pragma unroll
    for (int i = 0; i < 8; i++) {
        v8[i] += __shfl_xor_sync(0xffffffffu, v8[i], 8);
        v8[i] += __shfl_xor_sync(0xffffffffu, v8[i], 16);
    }

    int ch = (lane & 7) * 8;
    #pragma unroll
    for (int i = 0; i < 8; i++) v8[i] = v8[i] * 0.25f + b[ch + i];

    float sum = 0.f, ssq = 0.f;
    #pragma unroll
    for (int i = 0; i < 8; i++) { sum += v8[i]; ssq += v8[i] * v8[i]; }
    #pragma unroll
    for (int o = 16; o > 0; o >>= 1) {
        sum += __shfl_xor_sync(0xffffffffu, sum, o);
        ssq += __shfl_xor_sync(0xffffffffu, ssq, o);
    }
    float mean = sum * (1.f / 256.f);
    float var  = ssq * (1.f / 256.f) - mean * mean;
    float inv  = rsqrtf(var + 1e-5f);

    #pragma unroll
    for (int i = 0; i < 8; i++)
        v8[i] = fmaxf((v8[i] - mean) * inv * g[ch + i] + be[ch + i], 0.f);

    if (lane < 8) {
        float4 o0 = make_float4(v8[0], v8[1], v8[2], v8[3]);
        float4 o1 = make_float4(v8[4], v8[5], v8[6], v8[7]);
        float4* op = reinterpret_cast<float4*>(out + (long)warp * HID + ch);
        op[0] = o0; op[1] = o1;
    }
}

// ---------------------------------------------------------------------------
extern "C" void kernel_launch(void* const* d_in, const int* in_sizes, int n_in,
                              void* d_out, int out_size) {
    const float* x     = (const float*)d_in[0];
    const int*   ei    = (const int*)  d_in[1];
    const float* W1    = (const float*)d_in[2];
    const float* asrc1 = (const float*)d_in[3];
    const float* adst1 = (const float*)d_in[4];
    const float* b1    = (const float*)d_in[5];
    const float* g1    = (const float*)d_in[6];
    const float* be1   = (const float*)d_in[7];
    const float* W2    = (const float*)d_in[8];
    const float* asrc2 = (const float*)d_in[9];
    const float* adst2 = (const float*)d_in[10];
    const float* b2    = (const float*)d_in[11];
    const float* g2    = (const float*)d_in[12];
    const float* be2   = (const float*)d_in[13];
    const float* Wo    = (const float*)d_in[14];
    const float* bo    = (const float*)d_in[15];
    float* out = (float*)d_out;

    const int Nn   = in_sizes[0] / INC;      // 50000
    const int Ein  = in_sizes[1] / 2;        // 800000
    const int Etot = Ein + Nn;               // 850000
    const int nchunk = (Nn + 1023) / 1024;

    __half *H, *W4;
    float *ES, *ED, *F1, *F2, *WSD1, *WSD2;
    int *DEG, *CUR, *ROW, *COL, *CDST;
    cudaGetSymbolAddress((void**)&H,    g_H);
    cudaGetSymbolAddress((void**)&ES,   g_ES);
    cudaGetSymbolAddress((void**)&ED,   g_ED);
    cudaGetSymbolAddress((void**)&F1,   g_F1);
    cudaGetSymbolAddress((void**)&F2,   g_F2);
    cudaGetSymbolAddress((void**)&WSD1, g_WSD1);
    cudaGetSymbolAddress((void**)&WSD2, g_WSD2);
    cudaGetSymbolAddress((void**)&W4,   g_W4);
    cudaGetSymbolAddress((void**)&DEG,  g_DEG);
    cudaGetSymbolAddress((void**)&CUR,  g_CUR);
    cudaGetSymbolAddress((void**)&ROW,  g_ROW);
    cudaGetSymbolAddress((void**)&COL,  g_COL);
    cudaGetSymbolAddress((void**)&CDST, g_CDST);

    // lazy side stream + events (created on first, uncaptured, call)
    static cudaStream_t s1 = nullptr;
    static cudaEvent_t ev0 = nullptr, ev1, ev2, ev3, ev4;
    if (!s1) {
        cudaStreamCreateWithFlags(&s1, cudaStreamNonBlocking);
        cudaEventCreateWithFlags(&ev0, cudaEventDisableTiming);
        cudaEventCreateWithFlags(&ev1, cudaEventDisableTiming);
        cudaEventCreateWithFlags(&ev2, cudaEventDisableTiming);
        cudaEventCreateWithFlags(&ev3, cudaEventDisableTiming);
        cudaEventCreateWithFlags(&ev4, cudaEventDisableTiming);
    }

    dim3 gemm1_grid(HH / 128, (Nn + 127) / 128);
    dim3 gemm2_grid(HH / 128, (Nn + 127) / 128);
    dim3 gemmo_grid(OUTC / 128, (Nn + 127) / 128);
    int edge_blocks  = (Etot + 255) / 256;
    int node_warpblk = (Nn * 32 + 255) / 256;
    int score_blocks = (Nn + 7) / 8;
    dim3 fold_grid((INC * 8 + 7) / 8, 2);   // warp-per-output

    // ---- fork at t=0: side = foldw2 + sscore1; main = CSR build ------------
    cudaEventRecord(ev0, 0);
    cudaStreamWaitEvent(s1, ev0, 0);
    foldw2_k<<<fold_grid, 256, 0, s1>>>(W1, asrc1, adst1, WSD1, W2, asrc2, adst2, WSD2);
    sscore_k<<<score_blocks, 256, 0, s1>>>(x, WSD1, ES, ED, Nn, INC);

    cudaMemsetAsync(DEG, 0, (size_t)Nn * sizeof(int), 0);
    deg_k<<<edge_blocks, 256>>>(ei, DEG, Ein, Etot);
    rowptr_k<<<nchunk, 1024>>>(DEG, ROW, CUR, Nn, nchunk);
    fill_k<<<edge_blocks, 256>>>(ei, CUR, COL, CDST, Ein, Etot);
    cudaEventRecord(ev1, 0);                 // CSR (COL/CDST) ready

    // side: edgew1 (needs COL/CDST + ES/ED) runs concurrent with gemm1
    cudaStreamWaitEvent(s1, ev1, 0);
    edgew_k<<<edge_blocks, 256, 0, s1>>>(COL, CDST, ES, ED, W4, Etot);
    cudaEventRecord(ev2, s1);

    tgemm128<<<gemm1_grid, 256>>>(x, W1, (float*)H, Nn, HH, INC, nullptr, 1);
    cudaStreamWaitEvent(0, ev2, 0);
    gather_k<<<node_warpblk, 256>>>(H, ROW, COL, W4, b1, g1, be1, F1, Nn);

    // ---- layer 2: side = sscore2 + edgew2 || main = gemm2 ------------------
    cudaEventRecord(ev3, 0);
    cudaStreamWaitEvent(s1, ev3, 0);
    sscore_k<<<score_blocks, 256, 0, s1>>>(F1, WSD2, ES, ED, Nn, HID);
    edgew_k<<<edge_blocks, 256, 0, s1>>>(COL, CDST, ES, ED, W4, Etot);
    cudaEventRecord(ev4, s1);

    tgemm128<<<gemm2_grid, 256>>>(F1, W2, (float*)H, Nn, HH, HID, nullptr, 1);
    cudaStreamWaitEvent(0, ev4, 0);
    gather_k<<<node_warpblk, 256>>>(H, ROW, COL, W4, b2, g2, be2, F2, Nn);

    // ---- output projection (fp32 out) --------------------------------------
    tgemm128<<<gemmo_grid, 256>>>(F2, Wo, out, Nn, OUTC, HID, bo, 0);
}

// round 17
// speedup vs baseline: 1.2402x; 1.0236x over previous
#include <cuda_runtime.h>
#include <cuda_fp16.h>
#include <cstdint>

#define NNODES 50000
#define NEDGES 800000
#define ETOT   (NNODES + NEDGES)
#define HEADS  4
#define HID    64
#define HH     256   // HEADS*HID
#define INC    128
#define OUTC   128

// ---------------- scratch (device globals; no allocation) ----------------
__device__ __half g_H [NNODES * HH];      // transformed features, fp16 [N,4,64]
__device__ float g_ES  [NNODES * HEADS];
__device__ float g_ED  [NNODES * HEADS];
__device__ float g_F1  [NNODES * HID];
__device__ float g_F2  [NNODES * HID];
__device__ float g_WSD1[INC * 8];
__device__ float g_WSD2[HID * 8];
__device__ __half g_W4 [(size_t)ETOT * HEADS];   // per-edge weights (fp16), CSR order
__device__ int   g_DEG[NNODES];
__device__ int   g_CUR[NNODES];
__device__ int   g_ROW[NNODES + 1];
__device__ int   g_COL[ETOT];             // src per CSR slot
__device__ int   g_CDST[ETOT];            // dst per CSR slot

// ---------------- helpers ----------------
__device__ __forceinline__ uint32_t f2tf32(float f) {
    uint32_t u;
    asm("cvt.rna.tf32.f32 %0, %1;" : "=r"(u) : "f"(f));
    return u;
}

__device__ __forceinline__ void mma_tf32(float* c, const uint32_t* a, const uint32_t* b) {
    asm volatile(
        "mma.sync.aligned.m16n8k8.row.col.f32.tf32.tf32.f32 "
        "{%0,%1,%2,%3}, {%4,%5,%6,%7}, {%8,%9}, {%0,%1,%2,%3};\n"
        : "+f"(c[0]), "+f"(c[1]), "+f"(c[2]), "+f"(c[3])
        : "r"(a[0]), "r"(a[1]), "r"(a[2]), "r"(a[3]), "r"(b[0]), "r"(b[1]));
}

// ---------------- TF32 tensor-core GEMM, optional fp16 output (R10) ---------
#define ALD 20
#define BLD 136

__global__ __launch_bounds__(256, 2)
void tgemm128(const float* __restrict__ A, const float* __restrict__ B,
              float* __restrict__ C, int M, int Nn, int K,
              const float* __restrict__ bias, int half_out) {
    const int BM = 128, BK = 16;
    __shared__ uint32_t As[2][BM * ALD];
    __shared__ uint32_t Bs[2][BK * BLD];

    int tid  = threadIdx.x;
    int brow = blockIdx.y * BM;
    int bcol = blockIdx.x * 128;
    int w    = tid >> 5, lane = tid & 31;
    int wm   = w & 1, wn = w >> 1;
    int g    = lane >> 2, tg = lane & 3;

    int ar = tid >> 2, ac = (tid & 3) * 4;
    int br = tid >> 5, bc = (tid & 31) * 4;

    const int T = K / BK;
    float acc[4][4][4];
    #pragma unroll
    for (int i = 0; i < 4; i++)
        #pragma unroll
        for (int j = 0; j < 4; j++)
            #pragma unroll
            for (int r = 0; r < 4; r++) acc[i][j][r] = 0.f;

    {
        float4 va0 = make_float4(0.f,0.f,0.f,0.f), va1 = va0;
        long r0 = brow + ar, r1 = brow + ar + 64;
        if (r0 < M) va0 = *reinterpret_cast<const float4*>(A + r0 * K + ac);
        if (r1 < M) va1 = *reinterpret_cast<const float4*>(A + r1 * K + ac);
        uint32_t* d0 = &As[0][ar * ALD + ac];
        d0[0]=f2tf32(va0.x); d0[1]=f2tf32(va0.y); d0[2]=f2tf32(va0.z); d0[3]=f2tf32(va0.w);
        uint32_t* d1 = &As[0][(ar + 64) * ALD + ac];
        d1[0]=f2tf32(va1.x); d1[1]=f2tf32(va1.y); d1[2]=f2tf32(va1.z); d1[3]=f2tf32(va1.w);
        float4 vb0 = *reinterpret_cast<const float4*>(B + (long)br * Nn + bcol + bc);
        float4 vb1 = *reinterpret_cast<const float4*>(B + (long)(br + 8) * Nn + bcol + bc);
        uint32_t* e0 = &Bs[0][br * BLD + bc];
        e0[0]=f2tf32(vb0.x); e0[1]=f2tf32(vb0.y); e0[2]=f2tf32(vb0.z); e0[3]=f2tf32(vb0.w);
        uint32_t* e1 = &Bs[0][(br + 8) * BLD + bc];
        e1[0]=f2tf32(vb1.x); e1[1]=f2tf32(vb1.y); e1[2]=f2tf32(vb1.z); e1[3]=f2tf32(vb1.w);
    }
    __syncthreads();

    for (int t = 0; t < T; t++) {
        int buf = t & 1;
        float4 va0 = make_float4(0.f,0.f,0.f,0.f), va1 = va0, vb0 = va0, vb1 = va0;
        if (t + 1 < T) {
            int k0 = (t + 1) * BK;
            long r0 = brow + ar, r1 = brow + ar + 64;
            if (r0 < M) va0 = *reinterpret_cast<const float4*>(A + r0 * K + k0 + ac);
            if (r1 < M) va1 = *reinterpret_cast<const float4*>(A + r1 * K + k0 + ac);
            vb0 = *reinterpret_cast<const float4*>(B + (long)(k0 + br) * Nn + bcol + bc);
            vb1 = *reinterpret_cast<const float4*>(B + (long)(k0 + br + 8) * Nn + bcol + bc);
        }
        #pragma unroll
        for (int kk = 0; kk < BK; kk += 8) {
            uint32_t af[4][4];
            #pragma unroll
            for (int mt = 0; mt < 4; mt++) {
                int r0 = (wm * 64 + mt * 16 + g) * ALD + kk + tg;
                af[mt][0] = As[buf][r0];
                af[mt][1] = As[buf][r0 + 8 * ALD];
                af[mt][2] = As[buf][r0 + 4];
                af[mt][3] = As[buf][r0 + 8 * ALD + 4];
            }
            uint32_t bf[4][2];
            #pragma unroll
            for (int nt = 0; nt < 4; nt++) {
                int c0 = wn * 32 + nt * 8 + g;
                bf[nt][0] = Bs[buf][(kk + tg) * BLD + c0];
                bf[nt][1] = Bs[buf][(kk + tg + 4) * BLD + c0];
            }
            #pragma unroll
            for (int mt = 0; mt < 4; mt++)
                #pragma unroll
                for (int nt = 0; nt < 4; nt++)
                    mma_tf32(acc[mt][nt], af[mt], bf[nt]);
        }
        if (t + 1 < T) {
            int nb = buf ^ 1;
            uint32_t* d0 = &As[nb][ar * ALD + ac];
            d0[0]=f2tf32(va0.x); d0[1]=f2tf32(va0.y); d0[2]=f2tf32(va0.z); d0[3]=f2tf32(va0.w);
            uint32_t* d1 = &As[nb][(ar + 64) * ALD + ac];
            d1[0]=f2tf32(va1.x); d1[1]=f2tf32(va1.y); d1[2]=f2tf32(va1.z); d1[3]=f2tf32(va1.w);
            uint32_t* e0 = &Bs[nb][br * BLD + bc];
            e0[0]=f2tf32(vb0.x); e0[1]=f2tf32(vb0.y); e0[2]=f2tf32(vb0.z); e0[3]=f2tf32(vb0.w);
            uint32_t* e1 = &Bs[nb][(br + 8) * BLD + bc];
            e1[0]=f2tf32(vb1.x); e1[1]=f2tf32(vb1.y); e1[2]=f2tf32(vb1.z); e1[3]=f2tf32(vb1.w);
            __syncthreads();
        }
    }

    #pragma unroll
    for (int mt = 0; mt < 4; mt++) {
        #pragma unroll
        for (int nt = 0; nt < 4; nt++) {
            int r = brow + wm * 64 + mt * 16 + g;
            int c = bcol + wn * 32 + nt * 8 + tg * 2;
            float bx = 0.f, by = 0.f;
            if (bias) { bx = bias[c]; by = bias[c + 1]; }
            float2 v0 = make_float2(acc[mt][nt][0] + bx, acc[mt][nt][1] + by);
            float2 v1 = make_float2(acc[mt][nt][2] + bx, acc[mt][nt][3] + by);
            if (half_out) {
                __half* Ch = reinterpret_cast<__half*>(C);
                if (r < M)
                    *reinterpret_cast<__half2*>(Ch + (long)r * Nn + c) = __float22half2_rn(v0);
                if (r + 8 < M)
                    *reinterpret_cast<__half2*>(Ch + (long)(r + 8) * Nn + c) = __float22half2_rn(v1);
            } else {
                if (r < M)
                    *reinterpret_cast<float2*>(C + (long)r * Nn + c) = v0;
                if (r + 8 < M)
                    *reinterpret_cast<float2*>(C + (long)(r + 8) * Nn + c) = v1;
            }
        }
    }
}

// ---------------- fold attention vectors into W (warp per output) -----------
__global__ void foldw2_k(const float* __restrict__ W1, const float* __restrict__ as1,
                         const float* __restrict__ ad1, float* __restrict__ wsd1,
                         const float* __restrict__ W2, const float* __restrict__ as2,
                         const float* __restrict__ ad2, float* __restrict__ wsd2) {
    int layer = blockIdx.y;
    const float* W   = layer ? W2  : W1;
    const float* as_ = layer ? as2 : as1;
    const float* ad_ = layer ? ad2 : ad1;
    float* wsd = layer ? wsd2 : wsd1;
    int K = layer ? HID : INC;
    int gw   = blockIdx.x * 8 + (threadIdx.x >> 5);
    int lane = threadIdx.x & 31;
    if (gw >= K * 8) return;
    int k = gw >> 3, j = gw & 7, h = j & 3;
    const float* a  = ((j < 4) ? as_ : ad_) + h * HID;
    const float* wr = W + (long)k * HH + h * HID;
    float s = wr[lane] * a[lane] + wr[lane + 32] * a[lane + 32];
    #pragma unroll
    for (int o = 16; o > 0; o >>= 1)
        s += __shfl_xor_sync(0xffffffffu, s, o);
    if (lane == 0) wsd[gw] = s;
}

// ---------------- skinny scores: es/ed[n][h] = X[n,:] @ Wsd[:,j] ------------
__global__ void sscore_k(const float* __restrict__ X, const float* __restrict__ wsd,
                         float* __restrict__ es, float* __restrict__ ed,
                         int Nn, int K) {
    __shared__ float sW[8][128];
    int tid = threadIdx.x;
    for (int idx = tid; idx < K * 8; idx += blockDim.x) {
        int k = idx >> 3, j = idx & 7;
        sW[j][k] = wsd[k * 8 + j];
    }
    __syncthreads();

    int node = blockIdx.x * 8 + (tid >> 5);
    int lane = tid & 31;
    if (node >= Nn) return;
    int nq = K >> 2;

    float4 xv = make_float4(0.f, 0.f, 0.f, 0.f);
    if (lane < nq)
        xv = reinterpret_cast<const float4*>(X + (long)node * K)[lane];

    float acc[8];
    #pragma unroll
    for (int j = 0; j < 8; j++) {
        float4 wv = make_float4(0.f, 0.f, 0.f, 0.f);
        if (lane < nq)
            wv = *reinterpret_cast<const float4*>(&sW[j][lane * 4]);
        acc[j] = xv.x * wv.x + xv.y * wv.y + xv.z * wv.z + xv.w * wv.w;
    }
    #pragma unroll
    for (int o = 16; o > 0; o >>= 1) {
        #pragma unroll
        for (int j = 0; j < 8; j++)
            acc[j] += __shfl_xor_sync(0xffffffffu, acc[j], o);
    }
    if (lane == 0) {
        *reinterpret_cast<float4*>(es + node * 4) = make_float4(acc[0], acc[1], acc[2], acc[3]);
        *reinterpret_cast<float4*>(ed + node * 4) = make_float4(acc[4], acc[5], acc[6], acc[7]);
    }
}

// ---------------- CSR build ----------------
__global__ void deg_k(const int* __restrict__ ei, int* __restrict__ deg,
                      int Ein, int Etot) {
    int e = blockIdx.x * blockDim.x + threadIdx.x;
    if (e >= Etot) return;
    int d = (e < Ein) ? ei[Ein + e] : e - Ein;
    atomicAdd(&deg[d], 1);
}

// rowptr with self-computed chunk offset; also seeds cur[] = rowptr[].
__global__ void rowptr_k(const int* __restrict__ deg, int* __restrict__ rowptr,
                         int* __restrict__ cur, int Nn, int nchunk) {
    __shared__ int wsum[32];
    __shared__ int chunk_off;
    int t = threadIdx.x, lane = t & 31, wid = t >> 5;
    int base = blockIdx.x * 1024;

    {
        int v = 0;
        for (int i = t; i < base; i += 1024) v += deg[i];
        #pragma unroll
        for (int o = 16; o > 0; o >>= 1) v += __shfl_xor_sync(0xffffffffu, v, o);
        if (lane == 0) wsum[wid] = v;
        __syncthreads();
        if (wid == 0) {
            int s = wsum[lane];
            #pragma unroll
            for (int o = 16; o > 0; o >>= 1) s += __shfl_xor_sync(0xffffffffu, s, o);
            if (lane == 0) chunk_off = s;
        }
        __syncthreads();
    }

    int i = base + t;
    int v = (i < Nn) ? deg[i] : 0;
    int x = v;
    #pragma unroll
    for (int o = 1; o < 32; o <<= 1) {
        int y = __shfl_up_sync(0xffffffffu, x, o);
        if (lane >= o) x += y;
    }
    if (lane == 31) wsum[wid] = x;
    __syncthreads();
    if (wid == 0) {
        int s = wsum[lane];
        #pragma unroll
        for (int o = 1; o < 32; o <<= 1) {
            int y = __shfl_up_sync(0xffffffffu, s, o);
            if (lane >= o) s += y;
        }
        wsum[lane] = s;
    }
    __syncthreads();
    int off = chunk_off + (wid > 0 ? wsum[wid - 1] : 0);
    if (i < Nn) {
        int rp = off + x - v;
        rowptr[i] = rp;
        cur[i]    = rp;
    }
    if (blockIdx.x == nchunk - 1 && t == 0)
        rowptr[Nn] = chunk_off + wsum[31];
}

__global__ void fill_k(const int* __restrict__ ei, int* __restrict__ cursor,
                       int* __restrict__ colsrc, int* __restrict__ coldst,
                       int Ein, int Etot) {
    int e = blockIdx.x * blockDim.x + threadIdx.x;
    if (e >= Etot) return;
    int s, d;
    if (e < Ein) { s = ei[e]; d = ei[Ein + e]; }
    else         { s = d = e - Ein; }
    int slot = atomicAdd(&cursor[d], 1);
    colsrc[slot] = s;
    coldst[slot] = d;
}

// ---------------- per-edge softmax weights (fp16, CSR order) ----------------
__global__ void edgew_k(const int* __restrict__ colsrc, const int* __restrict__ coldst,
                        const float* __restrict__ es, const float* __restrict__ ed,
                        __half* __restrict__ w4, int Etot) {
    int e = blockIdx.x * blockDim.x + threadIdx.x;
    if (e >= Etot) return;
    int s = colsrc[e], d = coldst[e];
    float4 a = *reinterpret_cast<const float4*>(es + (long)s * 4);
    float4 c = *reinterpret_cast<const float4*>(ed + (long)d * 4);
    float4 r;
    float v;
    v = a.x + c.x; v = (v > 0.f) ? v : 0.2f * v; r.x = __expf(v);
    v = a.y + c.y; v = (v > 0.f) ? v : 0.2f * v; r.y = __expf(v);
    v = a.z + c.z; v = (v > 0.f) ? v : 0.2f * v; r.z = __expf(v);
    v = a.w + c.w; v = (v > 0.f) ? v : 0.2f * v; r.w = __expf(v);
    union { __half2 h[2]; uint2 u; } cv;
    cv.h[0] = __float22half2_rn(make_float2(r.x, r.y));
    cv.h[1] = __float22half2_rn(make_float2(r.z, r.w));
    *reinterpret_cast<uint2*>(w4 + (long)e * 4) = cv.u;
}

// ---------------- fused gather (fp16 H, fp16 weights; lean registers) -------
__global__ void gather_k(const __half* __restrict__ H, const int* __restrict__ rowptr,
                         const int* __restrict__ colsrc, const __half* __restrict__ w4,
                         const float* __restrict__ b, const float* __restrict__ g,
                         const float* __restrict__ be,
                         float* __restrict__ out, int Nn) {
    int warp = (blockIdx.x * blockDim.x + threadIdx.x) >> 5;
    int lane = threadIdx.x & 31;
    if (warp >= Nn) return;
    const int head = lane >> 3;

    float acc[8] = {0.f,0.f,0.f,0.f,0.f,0.f,0.f,0.f};
    float den = 0.f;

    int beg = rowptr[warp], end = rowptr[warp + 1];
    const uint4* __restrict__ H4 = reinterpret_cast<const uint4*>(H);

    int e = beg;
    for (; e + 8 <= end; e += 8) {
        int s[8]; float wv[8];
        #pragma unroll
        for (int u = 0; u < 8; u++) {
            s[u]  = colsrc[e + u];
            wv[u] = __half2float(w4[(long)(e + u) * 4 + head]);
        }
        #pragma unroll
        for (int u = 0; u < 8; u++) {
            uint4 hv = H4[(long)s[u] * 32 + lane];
            const __half2* hp = reinterpret_cast<const __half2*>(&hv);
            float2 f0 = __half22float2(hp[0]);
            float2 f1 = __half22float2(hp[1]);
            float2 f2 = __half22float2(hp[2]);
            float2 f3 = __half22float2(hp[3]);
            den += wv[u];
            acc[0] += wv[u] * f0.x; acc[1] += wv[u] * f0.y;
            acc[2] += wv[u] * f1.x; acc[3] += wv[u] * f1.y;
            acc[4] += wv[u] * f2.x; acc[5] += wv[u] * f2.y;
            acc[6] += wv[u] * f3.x; acc[7] += wv[u] * f3.y;
        }
    }
    for (; e < end; e++) {
        int s0  = colsrc[e];
        float w0 = __half2float(w4[(long)e * 4 + head]);
        uint4 hv = H4[(long)s0 * 32 + lane];
        const __half2* hp = reinterpret_cast<const __half2*>(&hv);
        float2 f0 = __half22float2(hp[0]);
        float2 f1 = __half22float2(hp[1]);
        float2 f2 = __half22float2(hp[2]);
        float2 f3 = __half22float2(hp[3]);
        den += w0;
        acc[0] += w0 * f0.x; acc[1] += w0 * f0.y;
        acc[2] += w0 * f1.x; acc[3] += w0 * f1.y;
        acc[4] += w0 * f2.x; acc[5] += w0 * f2.y;
        acc[6] += w0 * f3.x; acc[7] += w0 * f3.y;
    }

    float r = 1.f / den;
    float v8[8];
    #pragma unroll
    for (int i = 0; i < 8; i++) v8[i] = acc[i] * r;

    #pragma unroll
    for (int i = 0; i < 8; i++) {
        v8[i] += __shfl_xor_sync(0xffffffffu, v8[i], 8);
        v8[i] += __shfl_xor_sync(0xffffffffu, v8[i], 16);
    }

    int ch = (lane & 7) * 8;
    #pragma unroll
    for (int i = 0; i < 8; i++) v8[i] = v8[i] * 0.25f + b[ch + i];

    float sum = 0.f, ssq = 0.f;
    #pragma unroll
    for (int i = 0; i < 8; i++) { sum += v8[i]; ssq += v8[i] * v8[i]; }
    #pragma unroll
    for (int o = 16; o > 0; o >>= 1) {
        sum += __shfl_xor_sync(0xffffffffu, sum, o);
        ssq += __shfl_xor_sync(0xffffffffu, ssq, o);
    }
    float mean = sum * (1.f / 256.f);
    float var  = ssq * (1.f / 256.f) - mean * mean;
    float inv  = rsqrtf(var + 1e-5f);

    #pragma unroll
    for (int i = 0; i < 8; i++)
        v8[i] = fmaxf((v8[i] - mean) * inv * g[ch + i] + be[ch + i], 0.f);

    if (lane < 8) {
        float4 o0 = make_float4(v8[0], v8[1], v8[2], v8[3]);
        float4 o1 = make_float4(v8[4], v8[5], v8[6], v8[7]);
        float4* op = reinterpret_cast<float4*>(out + (long)warp * HID + ch);
        op[0] = o0; op[1] = o1;
    }
}

// ---------------------------------------------------------------------------
extern "C" void kernel_launch(void* const* d_in, const int* in_sizes, int n_in,
                              void* d_out, int out_size) {
    const float* x     = (const float*)d_in[0];
    const int*   ei    = (const int*)  d_in[1];
    const float* W1    = (const float*)d_in[2];
    const float* asrc1 = (const float*)d_in[3];
    const float* adst1 = (const float*)d_in[4];
    const float* b1    = (const float*)d_in[5];
    const float* g1    = (const float*)d_in[6];
    const float* be1   = (const float*)d_in[7];
    const float* W2    = (const float*)d_in[8];
    const float* asrc2 = (const float*)d_in[9];
    const float* adst2 = (const float*)d_in[10];
    const float* b2    = (const float*)d_in[11];
    const float* g2    = (const float*)d_in[12];
    const float* be2   = (const float*)d_in[13];
    const float* Wo    = (const float*)d_in[14];
    const float* bo    = (const float*)d_in[15];
    float* out = (float*)d_out;

    const int Nn   = in_sizes[0] / INC;      // 50000
    const int Ein  = in_sizes[1] / 2;        // 800000
    const int Etot = Ein + Nn;               // 850000
    const int nchunk = (Nn + 1023) / 1024;

    __half *H, *W4;
    float *ES, *ED, *F1, *F2, *WSD1, *WSD2;
    int *DEG, *CUR, *ROW, *COL, *CDST;
    cudaGetSymbolAddress((void**)&H,    g_H);
    cudaGetSymbolAddress((void**)&ES,   g_ES);
    cudaGetSymbolAddress((void**)&ED,   g_ED);
    cudaGetSymbolAddress((void**)&F1,   g_F1);
    cudaGetSymbolAddress((void**)&F2,   g_F2);
    cudaGetSymbolAddress((void**)&WSD1, g_WSD1);
    cudaGetSymbolAddress((void**)&WSD2, g_WSD2);
    cudaGetSymbolAddress((void**)&W4,   g_W4);
    cudaGetSymbolAddress((void**)&DEG,  g_DEG);
    cudaGetSymbolAddress((void**)&CUR,  g_CUR);
    cudaGetSymbolAddress((void**)&ROW,  g_ROW);
    cudaGetSymbolAddress((void**)&COL,  g_COL);
    cudaGetSymbolAddress((void**)&CDST, g_CDST);

    // lazy side streams + events (created on first, uncaptured, call)
    static cudaStream_t s1 = nullptr, s2 = nullptr;
    static cudaEvent_t ev0 = nullptr, evCSR, evW1, ev3, ev4;
    if (!s1) {
        cudaStreamCreateWithFlags(&s1, cudaStreamNonBlocking);
        cudaStreamCreateWithFlags(&s2, cudaStreamNonBlocking);
        cudaEventCreateWithFlags(&ev0,   cudaEventDisableTiming);
        cudaEventCreateWithFlags(&evCSR, cudaEventDisableTiming);
        cudaEventCreateWithFlags(&evW1,  cudaEventDisableTiming);
        cudaEventCreateWithFlags(&ev3,   cudaEventDisableTiming);
        cudaEventCreateWithFlags(&ev4,   cudaEventDisableTiming);
    }

    dim3 gemm1_grid(HH / 128, (Nn + 127) / 128);
    dim3 gemm2_grid(HH / 128, (Nn + 127) / 128);
    dim3 gemmo_grid(OUTC / 128, (Nn + 127) / 128);
    int edge_blocks  = (Etot + 255) / 256;
    int node_warpblk = (Nn * 32 + 255) / 256;
    int score_blocks = (Nn + 7) / 8;
    dim3 fold_grid((INC * 8 + 7) / 8, 2);   // warp-per-output

    // ---- three-way front fork ----------------------------------------------
    // main: gemm1 (depends only on x, W1)
    // s1  : CSR build (memset -> deg -> rowptr -> fill)
    // s2  : foldw2 -> sscore1, then (after CSR) edgew1
    cudaEventRecord(ev0, 0);
    cudaStreamWaitEvent(s1, ev0, 0);
    cudaStreamWaitEvent(s2, ev0, 0);

    cudaMemsetAsync(DEG, 0, (size_t)Nn * sizeof(int), s1);
    deg_k<<<edge_blocks, 256, 0, s1>>>(ei, DEG, Ein, Etot);
    rowptr_k<<<nchunk, 1024, 0, s1>>>(DEG, ROW, CUR, Nn, nchunk);
    fill_k<<<edge_blocks, 256, 0, s1>>>(ei, CUR, COL, CDST, Ein, Etot);
    cudaEventRecord(evCSR, s1);

    foldw2_k<<<fold_grid, 256, 0, s2>>>(W1, asrc1, adst1, WSD1, W2, asrc2, adst2, WSD2);
    sscore_k<<<score_blocks, 256, 0, s2>>>(x, WSD1, ES, ED, Nn, INC);
    cudaStreamWaitEvent(s2, evCSR, 0);
    edgew_k<<<edge_blocks, 256, 0, s2>>>(COL, CDST, ES, ED, W4, Etot);
    cudaEventRecord(evW1, s2);

    tgemm128<<<gemm1_grid, 256>>>(x, W1, (float*)H, Nn, HH, INC, nullptr, 1);
    cudaStreamWaitEvent(0, evW1, 0);
    gather_k<<<node_warpblk, 256>>>(H, ROW, COL, W4, b1, g1, be1, F1, Nn);

    // ---- layer 2: side = sscore2 + edgew2 || main = gemm2 ------------------
    cudaEventRecord(ev3, 0);
    cudaStreamWaitEvent(s2, ev3, 0);
    sscore_k<<<score_blocks, 256, 0, s2>>>(F1, WSD2, ES, ED, Nn, HID);
    edgew_k<<<edge_blocks, 256, 0, s2>>>(COL, CDST, ES, ED, W4, Etot);
    cudaEventRecord(ev4, s2);

    tgemm128<<<gemm2_grid, 256>>>(F1, W2, (float*)H, Nn, HH, HID, nullptr, 1);
    cudaStreamWaitEvent(0, ev4, 0);
    gather_k<<<node_warpblk, 256>>>(H, ROW, COL, W4, b2, g2, be2, F2, Nn);

    // ---- output projection (fp32 out) --------------------------------------
    tgemm128<<<gemmo_grid, 256>>>(F2, Wo, out, Nn, OUTC, HID, bo, 0);
}